// round 11
// baseline (speedup 1.0000x reference)
#include <cuda_runtime.h>
#include <stdint.h>
#include <math.h>

#define Tt 512
#define SEQSZ (128*512*128)
#define OFF_EMU 16384
#define OFF_ESG (OFF_EMU + 1*SEQSZ)
#define OFF_DMU (OFF_EMU + 2*SEQSZ)
#define OFF_DSG (OFF_EMU + 3*SEQSZ)
#define OFF_PMU (OFF_EMU + 4*SEQSZ)
#define OFF_PSG (OFF_EMU + 5*SEQSZ)

// scratch (static device globals; no runtime alloc)
__device__ float g_Gx[65536*1024];
__device__ float g_Ex[65536*128];
__device__ float g_h [65536*256];
__device__ float g_z1[65536*128];
__device__ float g_PH[65536*128];
__device__ float g_DH[65536*128];
__device__ float g_Wgx[128*1024];
__device__ float g_Wex[128*128];
__device__ float g_Kp[8*8*512*4];
__device__ float g_gb[1024];
__device__ float g_eb[128];

typedef unsigned long long ull;

__device__ __forceinline__ float softplus_(float x){ return fmaxf(x,0.f)+log1pf(expf(-fabsf(x))); }
__device__ __forceinline__ float sigmoid_(float x){ return 1.f/(1.f+expf(-x)); }

__device__ __forceinline__ ull pack2_(float v){
    ull r; asm("mov.b64 %0, {%1, %1};" : "=l"(r) : "f"(v)); return r;
}
__device__ __forceinline__ void ffma2_(ull &d, ull a, ull b){
    asm("fma.rn.f32x2 %0, %1, %2, %0;" : "+l"(d) : "l"(a), "l"(b));
}
__device__ __forceinline__ unsigned mapa_(unsigned addr, unsigned rank){
    unsigned r; asm("mapa.shared::cluster.u32 %0, %1, %2;" : "=r"(r) : "r"(addr), "r"(rank));
    return r;
}
__device__ __forceinline__ void blkcp_(unsigned dst, unsigned src, unsigned bytes, unsigned mbar){
    asm volatile("cp.async.bulk.shared::cluster.shared::cta.mbarrier::complete_tx::bytes [%0], [%1], %2, [%3];"
        :: "r"(dst), "r"(src), "r"(bytes), "r"(mbar) : "memory");
}
__device__ __forceinline__ void fence_async_(){
    asm volatile("fence.proxy.async.shared::cta;" ::: "memory");
}
__device__ __forceinline__ void mbar_init_(unsigned mbar, unsigned cnt){
    asm volatile("mbarrier.init.shared.b64 [%0], %1;" :: "r"(mbar), "r"(cnt) : "memory");
}
__device__ __forceinline__ void mbar_expect_(unsigned mbar, unsigned bytes){
    asm volatile("mbarrier.arrive.expect_tx.shared.b64 _, [%0], %1;" :: "r"(mbar), "r"(bytes) : "memory");
}
__device__ __forceinline__ void mbar_wait_(unsigned mbar, unsigned parity){
    unsigned done;
    asm volatile("{\n\t.reg .pred p;\n\t"
        "mbarrier.try_wait.parity.acquire.cta.shared::cta.b64 p, [%1], %2;\n\t"
        "selp.b32 %0, 1, 0, p;\n\t}"
        : "=r"(done) : "r"(mbar), "r"(parity) : "memory");
    while(!done){
        asm volatile("{\n\t.reg .pred p;\n\t"
            "mbarrier.try_wait.parity.acquire.cta.shared::cta.b64 p, [%1], %2, 0x989680;\n\t"
            "selp.b32 %0, 1, 0, p;\n\t}"
            : "=r"(done) : "r"(mbar), "r"(parity) : "memory");
    }
}
#define BARN_(id,n) asm volatile("bar.sync %0, %1;" :: "r"(id), "r"(n) : "memory")
#define CLUSTER_SYNC_() do{ \
    asm volatile("barrier.cluster.arrive.aligned;" ::: "memory"); \
    asm volatile("barrier.cluster.wait.aligned;" ::: "memory"); }while(0)

// ------------------------- tiled SGEMM (epilogues) -------------------------
__global__ __launch_bounds__(256) void gemm_k(
    const float* __restrict__ A1,int lda1,int K1,
    const float* __restrict__ A2,int lda2,int K2,
    const float* __restrict__ W1,int ldw1,
    const float* __restrict__ W2,int ldw2,
    const float* __restrict__ bias,
    float* __restrict__ out,int N,int act,int btmode)
{
    __shared__ __align__(16) float As[8][128];
    __shared__ __align__(16) float Ws[8][64];
    const int bm=blockIdx.y*128, bn=blockIdx.x*64;
    const int tid=threadIdx.x;
    const int ty=tid>>4, tx=tid&15;
    const int lr=tid>>1, lc=(tid&1)*4;
    const int wr=tid>>6, wc=tid&63;
    float acc[8][4];
    #pragma unroll
    for(int i=0;i<8;i++)
      #pragma unroll
      for(int j=0;j<4;j++) acc[i][j]=0.f;
    for(int seg=0;seg<2;seg++){
        const float* A = seg? A2:A1;
        if(A==nullptr) continue;
        const float* W = seg? W2:W1;
        const int lda=seg?lda2:lda1, ldw=seg?ldw2:ldw1, K=seg?K2:K1;
        for(int k0=0;k0<K;k0+=8){
            float4 av = *(const float4*)(A + (size_t)(bm+lr)*lda + k0+lc);
            float w0 = W[(size_t)(k0+wr)*ldw + bn+wc];
            float w1 = W[(size_t)(k0+wr+4)*ldw + bn+wc];
            __syncthreads();
            As[lc+0][lr]=av.x; As[lc+1][lr]=av.y; As[lc+2][lr]=av.z; As[lc+3][lr]=av.w;
            Ws[wr][wc]=w0; Ws[wr+4][wc]=w1;
            __syncthreads();
            #pragma unroll
            for(int kk=0;kk<8;kk++){
                float a[8],w[4];
                *(float4*)&a[0]=*(const float4*)&As[kk][ty*8];
                *(float4*)&a[4]=*(const float4*)&As[kk][ty*8+4];
                *(float4*)&w[0]=*(const float4*)&Ws[kk][tx*4];
                #pragma unroll
                for(int i=0;i<8;i++)
                  #pragma unroll
                  for(int j=0;j<4;j++) acc[i][j]=fmaf(a[i],w[j],acc[i][j]);
            }
        }
    }
    #pragma unroll
    for(int i=0;i<8;i++){
        int r=bm+ty*8+i;
        #pragma unroll
        for(int j=0;j<4;j++){
            int n=bn+tx*4+j;
            float v=acc[i][j];
            if(bias) v+=bias[n];
            if(act==1) v=fmaxf(v,0.f);
            else if(act==2) v=softplus_(v);
            size_t idx;
            if(btmode){ int b=r&127, t=r>>7; idx=((size_t)b*Tt+t)*(size_t)N+n; }
            else idx=(size_t)r*N+n;
            out[idx]=v;
        }
    }
}

// prep: Kz permuted-coalesced copy + bias folds
__global__ __launch_bounds__(256) void prep_k(
    const float* __restrict__ lstm_kernel,
    const float* __restrict__ lstm_bias,
    const float* __restrict__ enc_h_w,
    const float* __restrict__ enc_h_b,
    const float* __restrict__ phi_x_b)
{
    if(blockIdx.x < 512){
        int idx = blockIdx.x*256 + threadIdx.x;
        int e=idx&3, tid=(idx>>2)&511, u=(idx>>11)&7, rank=idx>>14;
        int dcol=tid&127, dseg=tid>>7;
        int gcol=(dcol>>5)*256 + rank*32 + (dcol&31);
        int k=dseg*32 + u*4 + e;
        g_Kp[idx] = lstm_kernel[(size_t)(128+k)*1024 + gcol];
    } else {
        int jj = (blockIdx.x-512)*256 + threadIdx.x;
        if(jj<1024){
            float s=lstm_bias[jj];
            for(int f=0;f<128;f++) s=fmaf(phi_x_b[f],lstm_kernel[f*1024+jj],s);
            g_gb[jj]=s;
        } else if(jj<1152){
            int j=jj-1024;
            float s=enc_h_b[j];
            for(int f=0;f<128;f++) s=fmaf(phi_x_b[f],enc_h_w[f*128+j],s);
            g_eb[j]=s;
        }
    }
}

// wk: fused weights Wgx = phi_x_w @ Kx ; Wex = phi_x_w @ Wenc_x
__global__ __launch_bounds__(256) void wk_k(
    const float* __restrict__ phi_x_w,
    const float* __restrict__ lstm_kernel,
    const float* __restrict__ enc_h_w)
{
    int idx = blockIdx.x*256 + threadIdx.x;
    if(idx < 131072){
        int i=idx>>10, c=idx&1023;
        float s=0.f;
        for(int m=0;m<128;m++) s=fmaf(phi_x_w[i*128+m], lstm_kernel[(size_t)m*1024+c], s);
        g_Wgx[idx]=s;
    } else {
        int j=idx-131072;
        int i=j>>7, c=j&127;
        float s=0.f;
        for(int m=0;m<128;m++) s=fmaf(phi_x_w[i*128+m], enc_h_w[m*128+c], s);
        g_Wex[j]=s;
    }
}

// fused input GEMMs: bx<16 -> Gx (N=1024), bx>=16 -> Ex (N=128)
__global__ __launch_bounds__(256) void inputs_k(const float* __restrict__ x)
{
    __shared__ __align__(16) float As[8][128];
    __shared__ __align__(16) float Ws[8][64];
    const int isGx = (blockIdx.x < 16);
    const float* W  = isGx ? g_Wgx : g_Wex;
    const float* bs = isGx ? g_gb  : g_eb;
    float* out      = isGx ? g_Gx  : g_Ex;
    const int ldw   = isGx ? 1024 : 128;
    const int N     = ldw;
    const int bn    = (isGx ? blockIdx.x : (blockIdx.x-16))*64;
    const int bm=blockIdx.y*128;
    const int tid=threadIdx.x;
    const int ty=tid>>4, tx=tid&15;
    const int lr=tid>>1, lc=(tid&1)*4;
    const int wr=tid>>6, wc=tid&63;
    float acc[8][4];
    #pragma unroll
    for(int i=0;i<8;i++)
      #pragma unroll
      for(int j=0;j<4;j++) acc[i][j]=0.f;
    for(int k0=0;k0<128;k0+=8){
        float4 av = *(const float4*)(x + (size_t)(bm+lr)*128 + k0+lc);
        float w0 = W[(size_t)(k0+wr)*ldw + bn+wc];
        float w1 = W[(size_t)(k0+wr+4)*ldw + bn+wc];
        __syncthreads();
        As[lc+0][lr]=av.x; As[lc+1][lr]=av.y; As[lc+2][lr]=av.z; As[lc+3][lr]=av.w;
        Ws[wr][wc]=w0; Ws[wr+4][wc]=w1;
        __syncthreads();
        #pragma unroll
        for(int kk=0;kk<8;kk++){
            float a[8],w[4];
            *(float4*)&a[0]=*(const float4*)&As[kk][ty*8];
            *(float4*)&a[4]=*(const float4*)&As[kk][ty*8+4];
            *(float4*)&w[0]=*(const float4*)&Ws[kk][tx*4];
            #pragma unroll
            for(int i=0;i<8;i++)
              #pragma unroll
              for(int j=0;j<4;j++) acc[i][j]=fmaf(a[i],w[j],acc[i][j]);
        }
    }
    #pragma unroll
    for(int i=0;i<8;i++){
        int r=bm+ty*8+i;
        #pragma unroll
        for(int j=0;j<4;j++){
            int n=bn+tx*4+j;
            out[(size_t)r*N+n]=acc[i][j]+bs[n];
        }
    }
}

// ------- cluster recurrence, 2-group (X=rows0-3, Y=rows4-7) pipelined ------
#define S_R     0
#define S_WE    32768
#define S_WMU   36864
#define S_WSG   38912
#define S_WPZ   40960
#define S_HT    43008
#define S_ET    47104
#define S_ZT    48128
#define S_Z1T   49152
#define S_GP    50176
#define S_APA   52224
#define S_APB   52736
#define S_BIAS  53248
#define S_MB    53296
#define S_STE   53312
#define S_STZ   53440
#define S_STZ1  53568
#define S_STH   53696
#define S_TOTF  53952
#define SEQ_SMEM_BYTES (S_TOTF*4)

__global__ void __cluster_dims__(8,1,1) __launch_bounds__(512,1) seq_clu(
    const float* __restrict__ eps,
    const float* __restrict__ enc_h_w,
    const float* __restrict__ enc_mu_w, const float* __restrict__ enc_mu_b,
    const float* __restrict__ enc_sg_w, const float* __restrict__ enc_sg_b,
    const float* __restrict__ phi_z_w,  const float* __restrict__ phi_z_b,
    const float* __restrict__ lstm_rec,
    float* __restrict__ out)
{
    extern __shared__ __align__(16) float sm[];
    float* R_s    = sm + S_R;
    float* Wenc_s = sm + S_WE;
    float* Wmu_s  = sm + S_WMU;
    float* Wsg_s  = sm + S_WSG;
    float* Wpz_s  = sm + S_WPZ;
    float* hT     = sm + S_HT;
    float* eT     = sm + S_ET;
    float* zT     = sm + S_ZT;
    float* z1T    = sm + S_Z1T;
    float* gp     = sm + S_GP;
    float* apA    = sm + S_APA;
    float* apB    = sm + S_APB;
    float* bias_s = sm + S_BIAS;
    float* stgE   = sm + S_STE;
    float* stgZ   = sm + S_STZ;
    float* stgZ1  = sm + S_STZ1;
    float* stgH   = sm + S_STH;

    const unsigned smb = (unsigned)__cvta_generic_to_shared(sm);
    const unsigned mb0 = smb + S_MB*4;   // EX,EY,ZX,ZY,Z1X,Z1Y,HX,HY at +0,8,...,56

    const int tid  = threadIdx.x;
    const int rank = blockIdx.x & 7;
    const int cid  = blockIdx.x >> 3;

    for(int idx=tid; idx<256*128; idx+=512){
        int k=idx>>7, c=idx&127;
        int gcol=(c>>5)*256 + rank*32 + (c&31);
        R_s[idx] = lstm_rec[k*1024 + gcol];
    }
    for(int idx=tid; idx<256*16; idx+=512){
        int k=idx>>4, j=idx&15;
        Wenc_s[idx] = enc_h_w[(128+k)*128 + rank*16 + j];
    }
    for(int idx=tid; idx<128*16; idx+=512){
        int k=idx>>4, j=idx&15;
        Wmu_s[idx] = enc_mu_w[k*128 + rank*16 + j];
        Wsg_s[idx] = enc_sg_w[k*128 + rank*16 + j];
        Wpz_s[idx] = phi_z_w [k*128 + rank*16 + j];
    }
    if(tid<16){
        bias_s[tid]    = enc_mu_b[rank*16+tid];
        bias_s[16+tid] = enc_sg_b[rank*16+tid];
        bias_s[32+tid] = phi_z_b [rank*16+tid];
    }
    for(int idx=tid; idx<4096; idx+=512) hT[idx]=0.f;
    if(tid==0){
        #pragma unroll
        for(int i=0;i<8;i++) mbar_init_(mb0+i*8,1);
    }
    __syncthreads();
    CLUSTER_SYNC_();

    float c_st = 0.f;   // tid<256: cell (grp=tid>>7, row=(tid>>5)&3, j=tid&31)
    const int dcol = tid & 127, dseg = tid >> 7;

    for(int t=0; t<Tt; t++){
        const unsigned par = t & 1;
        const unsigned pprev = (t-1) & 1;
        const int cur = t & 1, nxt = cur ^ 1;
        const float* hX = hT + cur*2048;
        const float* hY = hT + cur*2048 + 1024;

        // E/Z/Z1 expects: previous phase drained during step t-1 -> safe at top
        if(tid==0){
            mbar_expect_(mb0+0,2048); mbar_expect_(mb0+8,2048);
            mbar_expect_(mb0+16,2048); mbar_expect_(mb0+24,2048);
            mbar_expect_(mb0+32,2048); mbar_expect_(mb0+40,2048);
        }

        // ---- prefetches ----
        float exv=0.f, epsv=0.f;
        if(tid<128){
            int gg=tid>>6, idx=tid&63, row=idx>>4, col=idx&15;
            size_t b=((size_t)(cid*8+gg*4+row)*Tt+t)*128 + rank*16 + col;
            exv=g_Ex[b]; epsv=eps[b];
        }
        float gxv[4];
        if(tid<256){
            int gg=tid>>7, o=tid&127, j=o&31, row=o>>5;
            size_t gb=((size_t)(cid*8+gg*4+row)*Tt+t)*1024 + rank*32 + j;
            #pragma unroll
            for(int q=0;q<4;q++) gxv[q]=g_Gx[gb+(size_t)q*256];
        }
        float w32[32];
        {
            const float4* kp4=(const float4*)g_Kp;
            #pragma unroll
            for(int u=0;u<8;u++) *(float4*)&w32[u*4]=__ldg(&kp4[(rank*8+u)*512+tid]);
        }

        // ================= group X head =================
        if(t>0) mbar_wait_(mb0+48, pprev);
        // HX expect: MUST come after the previous-phase wait (expect during a
        // pending phase merges into it -> deadlock). Arrive-before-expect from
        // fast remote CTAs is fine (tx count goes transiently negative).
        if(tid==0) mbar_expect_(mb0+48,4096);
        if(tid<128){
            int j=tid&31, row=tid>>5;
            g_h[((size_t)t*128+cid*8+row)*256 + rank*32+j] = hX[(rank*32+j)*4+row];
        }
        // aX
        {
            int seg=tid>>6, o=tid&63, row=o>>4, col=o&15;
            float s=0.f; int k0=seg*32;
            #pragma unroll 8
            for(int k=k0;k<k0+32;k++) s=fmaf(hX[k*4+row], Wenc_s[k*16+col], s);
            apA[tid]=s;
        }
        __syncthreads();
        if(tid<64){
            int row=tid>>4, col=tid&15;
            float v=exv;
            #pragma unroll
            for(int s8=0;s8<8;s8++) v+=apA[s8*64+tid];
            stgE[col*4+row]=fmaxf(v,0.f);
            BARN_(1,64);
            if(tid==0){
                fence_async_();
                unsigned la = smb + (unsigned)(S_ET + rank*64)*4u;
                #pragma unroll
                for(unsigned rk=0;rk<8;rk++) blkcp_(mapa_(la,rk), smb+(unsigned)S_STE*4u, 256u, mapa_(mb0+0,rk));
            }
        }
        // ================= group Y head =================
        if(t>0) mbar_wait_(mb0+56, pprev);
        if(tid==0) mbar_expect_(mb0+56,4096);
        if(tid>=128 && tid<256){
            int o=tid&127, j=o&31, row=o>>5;
            g_h[((size_t)t*128+cid*8+4+row)*256 + rank*32+j] = hY[(rank*32+j)*4+row];
        }
        // aY
        {
            int seg=tid>>6, o=tid&63, row=o>>4, col=o&15;
            float s=0.f; int k0=seg*32;
            #pragma unroll 8
            for(int k=k0;k<k0+32;k++) s=fmaf(hY[k*4+row], Wenc_s[k*16+col], s);
            apB[tid]=s;
        }
        __syncthreads();
        if(tid>=64 && tid<128){
            int idx=tid&63, row=idx>>4, col=idx&15;
            float v=exv;
            #pragma unroll
            for(int s8=0;s8<8;s8++) v+=apB[s8*64+idx];
            stgE[64+col*4+row]=fmaxf(v,0.f);
            BARN_(2,64);
            if(tid==64){
                fence_async_();
                unsigned la = smb + (unsigned)(S_ET + 512 + rank*64)*4u;
                #pragma unroll
                for(unsigned rk=0;rk<8;rk++) blkcp_(mapa_(la,rk), smb+(unsigned)(S_STE+64)*4u, 256u, mapa_(mb0+8,rk));
            }
        }
        // ================= bX =================
        mbar_wait_(mb0+0, par);
        {
            int seg=tid>>7, o=tid&127, typ=o&1, col=(o>>1)&15, row=o>>5;
            const float* W = typ ? Wsg_s : Wmu_s;
            float s=0.f; int k0=seg*32;
            #pragma unroll 8
            for(int k=k0;k<k0+32;k++) s=fmaf(eT[k*4+row], W[k*16+col], s);
            apA[tid]=s;
        }
        __syncthreads();
        if(tid<64){
            int row=tid>>4, col=tid&15;
            int o0=row*32+col*2;
            float mu=bias_s[col], sg=bias_s[16+col];
            #pragma unroll
            for(int s4=0;s4<4;s4++){ mu+=apA[s4*128+o0]; sg+=apA[s4*128+o0+1]; }
            sg=softplus_(sg);
            size_t b=((size_t)(cid*8+row)*Tt+t)*128 + rank*16 + col;
            out[OFF_EMU+b]=mu; out[OFF_ESG+b]=sg;
            stgZ[col*4+row]=fmaf(sg,epsv,mu);
            BARN_(1,64);
            if(tid==0){
                fence_async_();
                unsigned la = smb + (unsigned)(S_ZT + rank*64)*4u;
                #pragma unroll
                for(unsigned rk=0;rk<8;rk++) blkcp_(mapa_(la,rk), smb+(unsigned)S_STZ*4u, 256u, mapa_(mb0+16,rk));
            }
        }
        // ================= bY =================
        mbar_wait_(mb0+8, par);
        {
            int seg=tid>>7, o=tid&127, typ=o&1, col=(o>>1)&15, row=o>>5;
            const float* W = typ ? Wsg_s : Wmu_s;
            float s=0.f; int k0=seg*32;
            #pragma unroll 8
            for(int k=k0;k<k0+32;k++) s=fmaf(eT[512+k*4+row], W[k*16+col], s);
            apB[tid]=s;
        }
        __syncthreads();
        if(tid>=64 && tid<128){
            int idx=tid&63, row=idx>>4, col=idx&15;
            int o0=row*32+col*2;
            float mu=bias_s[col], sg=bias_s[16+col];
            #pragma unroll
            for(int s4=0;s4<4;s4++){ mu+=apB[s4*128+o0]; sg+=apB[s4*128+o0+1]; }
            sg=softplus_(sg);
            size_t b=((size_t)(cid*8+4+row)*Tt+t)*128 + rank*16 + col;
            out[OFF_EMU+b]=mu; out[OFF_ESG+b]=sg;
            stgZ[64+col*4+row]=fmaf(sg,epsv,mu);
            BARN_(2,64);
            if(tid==64){
                fence_async_();
                unsigned la = smb + (unsigned)(S_ZT + 512 + rank*64)*4u;
                #pragma unroll
                for(unsigned rk=0;rk<8;rk++) blkcp_(mapa_(la,rk), smb+(unsigned)(S_STZ+64)*4u, 256u, mapa_(mb0+24,rk));
            }
        }
        // ================= cX =================
        mbar_wait_(mb0+16, par);
        {
            int seg=tid>>6, o=tid&63, row=o>>4, col=o&15;
            float s=0.f; int k0=seg*16;
            #pragma unroll 8
            for(int k=k0;k<k0+16;k++) s=fmaf(zT[k*4+row], Wpz_s[k*16+col], s);
            apA[tid]=s;
        }
        __syncthreads();
        if(tid<64){
            int row=tid>>4, col=tid&15;
            float v=bias_s[32+col];
            #pragma unroll
            for(int s8=0;s8<8;s8++) v+=apA[s8*64+tid];
            v=fmaxf(v,0.f);
            g_z1[((size_t)t*128+cid*8+row)*128 + rank*16 + col]=v;
            if(t==Tt-1) out[(size_t)(cid*8+row)*128 + rank*16 + col]=v;
            stgZ1[col*4+row]=v;
            BARN_(1,64);
            if(tid==0){
                fence_async_();
                unsigned la = smb + (unsigned)(S_Z1T + rank*64)*4u;
                #pragma unroll
                for(unsigned rk=0;rk<8;rk++) blkcp_(mapa_(la,rk), smb+(unsigned)S_STZ1*4u, 256u, mapa_(mb0+32,rk));
            }
        }
        // ================= cY =================
        mbar_wait_(mb0+24, par);
        {
            int seg=tid>>6, o=tid&63, row=o>>4, col=o&15;
            float s=0.f; int k0=seg*16;
            #pragma unroll 8
            for(int k=k0;k<k0+16;k++) s=fmaf(zT[512+k*4+row], Wpz_s[k*16+col], s);
            apB[tid]=s;
        }
        __syncthreads();
        if(tid>=64 && tid<128){
            int idx=tid&63, row=idx>>4, col=idx&15;
            float v=bias_s[32+col];
            #pragma unroll
            for(int s8=0;s8<8;s8++) v+=apB[s8*64+idx];
            v=fmaxf(v,0.f);
            g_z1[((size_t)t*128+cid*8+4+row)*128 + rank*16 + col]=v;
            if(t==Tt-1) out[(size_t)(cid*8+4+row)*128 + rank*16 + col]=v;
            stgZ1[64+col*4+row]=v;
            BARN_(2,64);
            if(tid==64){
                fence_async_();
                unsigned la = smb + (unsigned)(S_Z1T + 512 + rank*64)*4u;
                #pragma unroll
                for(unsigned rk=0;rk<8;rk++) blkcp_(mapa_(la,rk), smb+(unsigned)(S_STZ1+64)*4u, 256u, mapa_(mb0+40,rk));
            }
        }
        // ================= d1: h@R both groups (covers Z1 flights) ========
        ull aX0=0ull,aX1=0ull,aY0=0ull,aY1=0ull;
        {
            const int kr0=dseg*64;
            #pragma unroll 4
            for(int kk=kr0;kk<kr0+64;kk++){
                ull w2 = pack2_(R_s[kk*128+dcol]);
                ulonglong2 px = *(const ulonglong2*)&hX[kk*4];
                ulonglong2 py = *(const ulonglong2*)&hY[kk*4];
                ffma2_(aX0,w2,px.x); ffma2_(aX1,w2,px.y);
                ffma2_(aY0,w2,py.x); ffma2_(aY1,w2,py.y);
            }
        }
        // ================= d2X + cellX =================
        mbar_wait_(mb0+32, par);
        {
            const int kz0=dseg*32;
            #pragma unroll 8
            for(int u=0;u<32;u++){
                ull w2 = pack2_(w32[u]);
                ulonglong2 zp = *(const ulonglong2*)&z1T[(kz0+u)*4];
                ffma2_(aX0,w2,zp.x); ffma2_(aX1,w2,zp.y);
            }
            ulonglong2 st; st.x=aX0; st.y=aX1;
            *(ulonglong2*)&gp[dseg*512 + dcol*4] = st;
        }
        __syncthreads();
        if(tid<128){
            int j=tid&31, row=tid>>5;
            float gi=gxv[0], gf=gxv[1], gg2=gxv[2], go=gxv[3];
            #pragma unroll
            for(int s4=0;s4<4;s4++){
                const float* p = gp + s4*512;
                gi +=p[(     j)*4+row]; gf +=p[(32+j)*4+row];
                gg2+=p[(64+j)*4+row]; go +=p[(96+j)*4+row];
            }
            float iv=sigmoid_(gi), fv=sigmoid_(gf), gv=tanhf(gg2), ov=sigmoid_(go);
            c_st = fv*c_st + iv*gv;
            float hv = ov*tanhf(c_st);
            stgH[j*4+row]=hv;
            BARN_(3,128);
            if(tid==0){
                fence_async_();
                unsigned la = smb + (unsigned)(S_HT + nxt*2048 + rank*128)*4u;
                #pragma unroll
                for(unsigned rk=0;rk<8;rk++) blkcp_(mapa_(la,rk), smb+(unsigned)S_STH*4u, 512u, mapa_(mb0+48,rk));
            }
        }
        __syncthreads();
        // ================= d2Y + cellY =================
        mbar_wait_(mb0+40, par);
        {
            const int kz0=dseg*32;
            #pragma unroll 8
            for(int u=0;u<32;u++){
                ull w2 = pack2_(w32[u]);
                ulonglong2 zp = *(const ulonglong2*)&z1T[512+(kz0+u)*4];
                ffma2_(aY0,w2,zp.x); ffma2_(aY1,w2,zp.y);
            }
            ulonglong2 st; st.x=aY0; st.y=aY1;
            *(ulonglong2*)&gp[dseg*512 + dcol*4] = st;
        }
        __syncthreads();
        if(tid>=128 && tid<256){
            int o=tid&127, j=o&31, row=o>>5;
            float gi=gxv[0], gf=gxv[1], gg2=gxv[2], go=gxv[3];
            #pragma unroll
            for(int s4=0;s4<4;s4++){
                const float* p = gp + s4*512;
                gi +=p[(     j)*4+row]; gf +=p[(32+j)*4+row];
                gg2+=p[(64+j)*4+row]; go +=p[(96+j)*4+row];
            }
            float iv=sigmoid_(gi), fv=sigmoid_(gf), gv=tanhf(gg2), ov=sigmoid_(go);
            c_st = fv*c_st + iv*gv;
            float hv = ov*tanhf(c_st);
            stgH[128+j*4+row]=hv;
            BARN_(4,128);
            if(tid==128){
                fence_async_();
                unsigned la = smb + (unsigned)(S_HT + nxt*2048 + 1024 + rank*128)*4u;
                #pragma unroll
                for(unsigned rk=0;rk<8;rk++) blkcp_(mapa_(la,rk), smb+(unsigned)(S_STH+128)*4u, 512u, mapa_(mb0+56,rk));
            }
        }
        __syncthreads();
    }
    mbar_wait_(mb0+48, (Tt-1)&1);
    mbar_wait_(mb0+56, (Tt-1)&1);
    CLUSTER_SYNC_();
}

extern "C" void kernel_launch(void* const* d_in, const int* in_sizes, int n_in,
                              void* d_out, int out_size)
{
    (void)in_sizes;(void)n_in;(void)out_size;
    const float* x           =(const float*)d_in[0];
    const float* eps         =(const float*)d_in[1];
    const float* prior_h_w   =(const float*)d_in[2];
    const float* prior_h_b   =(const float*)d_in[3];
    const float* prior_mu_w  =(const float*)d_in[4];
    const float* prior_mu_b  =(const float*)d_in[5];
    const float* prior_sg_w  =(const float*)d_in[6];
    const float* prior_sg_b  =(const float*)d_in[7];
    const float* phi_x_w     =(const float*)d_in[8];
    const float* phi_x_b     =(const float*)d_in[9];
    const float* enc_h_w     =(const float*)d_in[10];
    const float* enc_h_b     =(const float*)d_in[11];
    const float* enc_mu_w    =(const float*)d_in[12];
    const float* enc_mu_b    =(const float*)d_in[13];
    const float* enc_sg_w    =(const float*)d_in[14];
    const float* enc_sg_b    =(const float*)d_in[15];
    const float* phi_z_w     =(const float*)d_in[16];
    const float* phi_z_b     =(const float*)d_in[17];
    const float* dec_h_w     =(const float*)d_in[18];
    const float* dec_h_b     =(const float*)d_in[19];
    const float* dec_mu_w    =(const float*)d_in[20];
    const float* dec_mu_b    =(const float*)d_in[21];
    const float* dec_sg_w    =(const float*)d_in[22];
    const float* dec_sg_b    =(const float*)d_in[23];
    const float* lstm_kernel =(const float*)d_in[24];
    const float* lstm_rec    =(const float*)d_in[25];
    const float* lstm_bias   =(const float*)d_in[26];
    float* out=(float*)d_out;

    float *pH,*pZ1,*pPH,*pDH;
    cudaGetSymbolAddress((void**)&pH,  g_h);
    cudaGetSymbolAddress((void**)&pZ1, g_z1);
    cudaGetSymbolAddress((void**)&pPH, g_PH);
    cudaGetSymbolAddress((void**)&pDH, g_DH);

    cudaFuncSetAttribute(seq_clu, cudaFuncAttributeMaxDynamicSharedMemorySize, SEQ_SMEM_BYTES);

    // 1. prep (bias folds + coalesced Kz)
    prep_k<<<517,256>>>(lstm_kernel,lstm_bias,enc_h_w,enc_h_b,phi_x_b);
    // 2. fused weights
    wk_k<<<576,256>>>(phi_x_w,lstm_kernel,enc_h_w);
    // 3. fused big input GEMMs
    inputs_k<<<dim3(18,512),256>>>(x);
    // 4. sequential recurrence (launch #4 -> captured by ncu)
    seq_clu<<<128,512,SEQ_SMEM_BYTES>>>(eps, enc_h_w, enc_mu_w,enc_mu_b, enc_sg_w,enc_sg_b,
                                        phi_z_w,phi_z_b, lstm_rec, out);
    // 5-10. epilogues
    gemm_k<<<dim3(2,512),256>>>(pH,256,256, nullptr,0,0, prior_h_w,128, nullptr,0,
                                prior_h_b, pPH,128,1,0);
    gemm_k<<<dim3(2,512),256>>>(pPH,128,128, nullptr,0,0, prior_mu_w,128, nullptr,0,
                                prior_mu_b, out+OFF_PMU,128,0,1);
    gemm_k<<<dim3(2,512),256>>>(pPH,128,128, nullptr,0,0, prior_sg_w,128, nullptr,0,
                                prior_sg_b, out+OFF_PSG,128,2,1);
    gemm_k<<<dim3(2,512),256>>>(pZ1,128,128, pH,256,256, dec_h_w,128, dec_h_w+128*128,128,
                                dec_h_b, pDH,128,1,0);
    gemm_k<<<dim3(2,512),256>>>(pDH,128,128, nullptr,0,0, dec_mu_w,128, nullptr,0,
                                dec_mu_b, out+OFF_DMU,128,0,1);
    gemm_k<<<dim3(2,512),256>>>(pDH,128,128, nullptr,0,0, dec_sg_w,128, nullptr,0,
                                dec_sg_b, out+OFF_DSG,128,2,1);
}

// round 12
// speedup vs baseline: 1.2947x; 1.2947x over previous
#include <cuda_runtime.h>
#include <stdint.h>
#include <math.h>

#define Tt 512
#define SEQSZ (128*512*128)
#define OFF_EMU 16384
#define OFF_ESG (OFF_EMU + 1*SEQSZ)
#define OFF_DMU (OFF_EMU + 2*SEQSZ)
#define OFF_DSG (OFF_EMU + 3*SEQSZ)
#define OFF_PMU (OFF_EMU + 4*SEQSZ)
#define OFF_PSG (OFF_EMU + 5*SEQSZ)

// scratch (static device globals; no runtime alloc)
__device__ float g_Gx[65536*1024];
__device__ float g_Ex[65536*128];
__device__ float g_h [65536*256];
__device__ float g_z1[65536*128];
__device__ float g_PH[65536*128];
__device__ float g_DH[65536*128];
__device__ float g_Wgx[128*1024];
__device__ float g_Wex[128*128];
__device__ float g_Kp[8*8*512*4];
__device__ float g_gb[1024];
__device__ float g_eb[128];

typedef unsigned long long ull;

__device__ __forceinline__ float softplus_(float x){ return fmaxf(x,0.f)+log1pf(expf(-fabsf(x))); }
__device__ __forceinline__ float sigmoid_(float x){ return 1.f/(1.f+expf(-x)); }

__device__ __forceinline__ ull pack2_(float v){
    ull r; asm("mov.b64 %0, {%1, %1};" : "=l"(r) : "f"(v)); return r;
}
__device__ __forceinline__ void ffma2_(ull &d, ull a, ull b){
    asm("fma.rn.f32x2 %0, %1, %2, %0;" : "+l"(d) : "l"(a), "l"(b));
}
__device__ __forceinline__ void unpack2_(ull v, float &lo, float &hi){
    asm("mov.b64 {%0, %1}, %2;" : "=f"(lo), "=f"(hi) : "l"(v));
}
__device__ __forceinline__ unsigned mapa_(unsigned addr, unsigned rank){
    unsigned r; asm("mapa.shared::cluster.u32 %0, %1, %2;" : "=r"(r) : "r"(addr), "r"(rank));
    return r;
}
__device__ __forceinline__ void blkcp_(unsigned dst, unsigned src, unsigned bytes, unsigned mbar){
    asm volatile("cp.async.bulk.shared::cluster.shared::cta.mbarrier::complete_tx::bytes [%0], [%1], %2, [%3];"
        :: "r"(dst), "r"(src), "r"(bytes), "r"(mbar) : "memory");
}
__device__ __forceinline__ void fence_async_(){
    asm volatile("fence.proxy.async.shared::cta;" ::: "memory");
}
__device__ __forceinline__ void mbar_init_(unsigned mbar, unsigned cnt){
    asm volatile("mbarrier.init.shared.b64 [%0], %1;" :: "r"(mbar), "r"(cnt) : "memory");
}
__device__ __forceinline__ void mbar_expect_(unsigned mbar, unsigned bytes){
    asm volatile("mbarrier.arrive.expect_tx.shared.b64 _, [%0], %1;" :: "r"(mbar), "r"(bytes) : "memory");
}
__device__ __forceinline__ void mbar_wait_(unsigned mbar, unsigned parity){
    unsigned done;
    asm volatile("{\n\t.reg .pred p;\n\t"
        "mbarrier.try_wait.parity.acquire.cta.shared::cta.b64 p, [%1], %2;\n\t"
        "selp.b32 %0, 1, 0, p;\n\t}"
        : "=r"(done) : "r"(mbar), "r"(parity) : "memory");
    while(!done){
        asm volatile("{\n\t.reg .pred p;\n\t"
            "mbarrier.try_wait.parity.acquire.cta.shared::cta.b64 p, [%1], %2, 0x989680;\n\t"
            "selp.b32 %0, 1, 0, p;\n\t}"
            : "=r"(done) : "r"(mbar), "r"(parity) : "memory");
    }
}
#define CLUSTER_SYNC_() do{ \
    asm volatile("barrier.cluster.arrive.aligned;" ::: "memory"); \
    asm volatile("barrier.cluster.wait.aligned;" ::: "memory"); }while(0)

// ------------------------- tiled SGEMM (epilogues) -------------------------
__global__ __launch_bounds__(256) void gemm_k(
    const float* __restrict__ A1,int lda1,int K1,
    const float* __restrict__ A2,int lda2,int K2,
    const float* __restrict__ W1,int ldw1,
    const float* __restrict__ W2,int ldw2,
    const float* __restrict__ bias,
    float* __restrict__ out,int N,int act,int btmode)
{
    __shared__ __align__(16) float As[8][128];
    __shared__ __align__(16) float Ws[8][64];
    const int bm=blockIdx.y*128, bn=blockIdx.x*64;
    const int tid=threadIdx.x;
    const int ty=tid>>4, tx=tid&15;
    const int lr=tid>>1, lc=(tid&1)*4;
    const int wr=tid>>6, wc=tid&63;
    float acc[8][4];
    #pragma unroll
    for(int i=0;i<8;i++)
      #pragma unroll
      for(int j=0;j<4;j++) acc[i][j]=0.f;
    for(int seg=0;seg<2;seg++){
        const float* A = seg? A2:A1;
        if(A==nullptr) continue;
        const float* W = seg? W2:W1;
        const int lda=seg?lda2:lda1, ldw=seg?ldw2:ldw1, K=seg?K2:K1;
        for(int k0=0;k0<K;k0+=8){
            float4 av = *(const float4*)(A + (size_t)(bm+lr)*lda + k0+lc);
            float w0 = W[(size_t)(k0+wr)*ldw + bn+wc];
            float w1 = W[(size_t)(k0+wr+4)*ldw + bn+wc];
            __syncthreads();
            As[lc+0][lr]=av.x; As[lc+1][lr]=av.y; As[lc+2][lr]=av.z; As[lc+3][lr]=av.w;
            Ws[wr][wc]=w0; Ws[wr+4][wc]=w1;
            __syncthreads();
            #pragma unroll
            for(int kk=0;kk<8;kk++){
                float a[8],w[4];
                *(float4*)&a[0]=*(const float4*)&As[kk][ty*8];
                *(float4*)&a[4]=*(const float4*)&As[kk][ty*8+4];
                *(float4*)&w[0]=*(const float4*)&Ws[kk][tx*4];
                #pragma unroll
                for(int i=0;i<8;i++)
                  #pragma unroll
                  for(int j=0;j<4;j++) acc[i][j]=fmaf(a[i],w[j],acc[i][j]);
            }
        }
    }
    #pragma unroll
    for(int i=0;i<8;i++){
        int r=bm+ty*8+i;
        #pragma unroll
        for(int j=0;j<4;j++){
            int n=bn+tx*4+j;
            float v=acc[i][j];
            if(bias) v+=bias[n];
            if(act==1) v=fmaxf(v,0.f);
            else if(act==2) v=softplus_(v);
            size_t idx;
            if(btmode){ int b=r&127, t=r>>7; idx=((size_t)b*Tt+t)*(size_t)N+n; }
            else idx=(size_t)r*N+n;
            out[idx]=v;
        }
    }
}

// prep: Kz permuted-coalesced copy + bias folds
__global__ __launch_bounds__(256) void prep_k(
    const float* __restrict__ lstm_kernel,
    const float* __restrict__ lstm_bias,
    const float* __restrict__ enc_h_w,
    const float* __restrict__ enc_h_b,
    const float* __restrict__ phi_x_b)
{
    if(blockIdx.x < 512){
        int idx = blockIdx.x*256 + threadIdx.x;
        int e=idx&3, tid=(idx>>2)&511, u=(idx>>11)&7, rank=idx>>14;
        int dcol=tid&127, dseg=tid>>7;
        int gcol=(dcol>>5)*256 + rank*32 + (dcol&31);
        int k=dseg*32 + u*4 + e;
        g_Kp[idx] = lstm_kernel[(size_t)(128+k)*1024 + gcol];
    } else {
        int jj = (blockIdx.x-512)*256 + threadIdx.x;
        if(jj<1024){
            float s=lstm_bias[jj];
            for(int f=0;f<128;f++) s=fmaf(phi_x_b[f],lstm_kernel[f*1024+jj],s);
            g_gb[jj]=s;
        } else if(jj<1152){
            int j=jj-1024;
            float s=enc_h_b[j];
            for(int f=0;f<128;f++) s=fmaf(phi_x_b[f],enc_h_w[f*128+j],s);
            g_eb[j]=s;
        }
    }
}

// wk: fused weights Wgx = phi_x_w @ Kx ; Wex = phi_x_w @ Wenc_x
__global__ __launch_bounds__(256) void wk_k(
    const float* __restrict__ phi_x_w,
    const float* __restrict__ lstm_kernel,
    const float* __restrict__ enc_h_w)
{
    int idx = blockIdx.x*256 + threadIdx.x;
    if(idx < 131072){
        int i=idx>>10, c=idx&1023;
        float s=0.f;
        for(int m=0;m<128;m++) s=fmaf(phi_x_w[i*128+m], lstm_kernel[(size_t)m*1024+c], s);
        g_Wgx[idx]=s;
    } else {
        int j=idx-131072;
        int i=j>>7, c=j&127;
        float s=0.f;
        for(int m=0;m<128;m++) s=fmaf(phi_x_w[i*128+m], enc_h_w[m*128+c], s);
        g_Wex[j]=s;
    }
}

// fused input GEMMs: bx<16 -> Gx (N=1024), bx>=16 -> Ex (N=128)
__global__ __launch_bounds__(256) void inputs_k(const float* __restrict__ x)
{
    __shared__ __align__(16) float As[8][128];
    __shared__ __align__(16) float Ws[8][64];
    const int isGx = (blockIdx.x < 16);
    const float* W  = isGx ? g_Wgx : g_Wex;
    const float* bs = isGx ? g_gb  : g_eb;
    float* out      = isGx ? g_Gx  : g_Ex;
    const int ldw   = isGx ? 1024 : 128;
    const int N     = ldw;
    const int bn    = (isGx ? blockIdx.x : (blockIdx.x-16))*64;
    const int bm=blockIdx.y*128;
    const int tid=threadIdx.x;
    const int ty=tid>>4, tx=tid&15;
    const int lr=tid>>1, lc=(tid&1)*4;
    const int wr=tid>>6, wc=tid&63;
    float acc[8][4];
    #pragma unroll
    for(int i=0;i<8;i++)
      #pragma unroll
      for(int j=0;j<4;j++) acc[i][j]=0.f;
    for(int k0=0;k0<128;k0+=8){
        float4 av = *(const float4*)(x + (size_t)(bm+lr)*128 + k0+lc);
        float w0 = W[(size_t)(k0+wr)*ldw + bn+wc];
        float w1 = W[(size_t)(k0+wr+4)*ldw + bn+wc];
        __syncthreads();
        As[lc+0][lr]=av.x; As[lc+1][lr]=av.y; As[lc+2][lr]=av.z; As[lc+3][lr]=av.w;
        Ws[wr][wc]=w0; Ws[wr+4][wc]=w1;
        __syncthreads();
        #pragma unroll
        for(int kk=0;kk<8;kk++){
            float a[8],w[4];
            *(float4*)&a[0]=*(const float4*)&As[kk][ty*8];
            *(float4*)&a[4]=*(const float4*)&As[kk][ty*8+4];
            *(float4*)&w[0]=*(const float4*)&Ws[kk][tx*4];
            #pragma unroll
            for(int i=0;i<8;i++)
              #pragma unroll
              for(int j=0;j<4;j++) acc[i][j]=fmaf(a[i],w[j],acc[i][j]);
        }
    }
    #pragma unroll
    for(int i=0;i<8;i++){
        int r=bm+ty*8+i;
        #pragma unroll
        for(int j=0;j<4;j++){
            int n=bn+tx*4+j;
            out[(size_t)r*N+n]=acc[i][j]+bs[n];
        }
    }
}

// ---------------- cluster-distributed sequential recurrence ----------------
// R8 single-group structure + overlap edits (waitH at top, d1 3-way split,
// late Kz prefetch, 8-thread copy issue).
#define S_R    0
#define S_WE   32768
#define S_WMU  36864
#define S_WSG  38912
#define S_WPZ  40960
#define S_HT   43008
#define S_ET   47104
#define S_ZT   48128
#define S_Z1T  49152
#define S_GP   50176
#define S_AP   54272
#define S_BIAS 54784
#define S_MB   54832
#define S_STA  54840
#define S_STZ  54968
#define S_STZ1 55096
#define S_STH  55224
#define S_TOTF 55480
#define SEQ_SMEM_BYTES (S_TOTF*4)

__global__ void __cluster_dims__(8,1,1) __launch_bounds__(512,1) seq_clu(
    const float* __restrict__ eps,
    const float* __restrict__ enc_h_w,
    const float* __restrict__ enc_mu_w, const float* __restrict__ enc_mu_b,
    const float* __restrict__ enc_sg_w, const float* __restrict__ enc_sg_b,
    const float* __restrict__ phi_z_w,  const float* __restrict__ phi_z_b,
    const float* __restrict__ lstm_rec,
    float* __restrict__ out)
{
    extern __shared__ __align__(16) float sm[];
    float* R_s    = sm + S_R;
    float* Wenc_s = sm + S_WE;
    float* Wmu_s  = sm + S_WMU;
    float* Wsg_s  = sm + S_WSG;
    float* Wpz_s  = sm + S_WPZ;
    float* hT     = sm + S_HT;
    float* eT     = sm + S_ET;
    float* zT     = sm + S_ZT;
    float* z1T    = sm + S_Z1T;
    float* gp     = sm + S_GP;
    float* ap     = sm + S_AP;
    float* bias_s = sm + S_BIAS;
    float* stgA   = sm + S_STA;
    float* stgZ   = sm + S_STZ;
    float* stgZ1  = sm + S_STZ1;
    float* stgH   = sm + S_STH;

    const unsigned smb = (unsigned)__cvta_generic_to_shared(sm);
    const unsigned mbE  = smb + S_MB*4;
    const unsigned mbZ  = mbE + 8;
    const unsigned mbZ1 = mbE + 16;
    const unsigned mbH  = mbE + 24;

    const int tid  = threadIdx.x;
    const int rank = blockIdx.x & 7;
    const int cid  = blockIdx.x >> 3;

    for(int idx=tid; idx<256*128; idx+=512){
        int k=idx>>7, c=idx&127;
        int gcol=(c>>5)*256 + rank*32 + (c&31);
        R_s[idx] = lstm_rec[k*1024 + gcol];
    }
    for(int idx=tid; idx<256*16; idx+=512){
        int k=idx>>4, j=idx&15;
        Wenc_s[idx] = enc_h_w[(128+k)*128 + rank*16 + j];
    }
    for(int idx=tid; idx<128*16; idx+=512){
        int k=idx>>4, j=idx&15;
        Wmu_s[idx] = enc_mu_w[k*128 + rank*16 + j];
        Wsg_s[idx] = enc_sg_w[k*128 + rank*16 + j];
        Wpz_s[idx] = phi_z_w [k*128 + rank*16 + j];
    }
    if(tid<16){
        bias_s[tid]    = enc_mu_b[rank*16+tid];
        bias_s[16+tid] = enc_sg_b[rank*16+tid];
        bias_s[32+tid] = phi_z_b [rank*16+tid];
    }
    for(int idx=tid; idx<2*256*8; idx+=512) hT[idx]=0.f;
    if(tid==0){
        mbar_init_(mbE,1); mbar_init_(mbZ,1); mbar_init_(mbZ1,1); mbar_init_(mbH,1);
    }
    __syncthreads();
    CLUSTER_SYNC_();

    float c0_st = 0.f, c1_st = 0.f;

    const int dcol = tid & 127, dseg = tid >> 7;
    const unsigned laE  = smb + (unsigned)S_ET*4u  + (unsigned)rank*512u;
    const unsigned laZ  = smb + (unsigned)S_ZT*4u  + (unsigned)rank*512u;
    const unsigned laZ1 = smb + (unsigned)S_Z1T*4u + (unsigned)rank*512u;
    const unsigned srcA  = smb + (unsigned)S_STA*4u;
    const unsigned srcZ  = smb + (unsigned)S_STZ*4u;
    const unsigned srcZ1 = smb + (unsigned)S_STZ1*4u;
    const unsigned srcH  = smb + (unsigned)S_STH*4u;

    for(int t=0; t<Tt; t++){
        const unsigned par = t & 1;
        float* hTc = hT + (t&1)*2048;
        const unsigned hTn_off = (unsigned)(S_HT + ((t+1)&1)*2048);

        // E/Z/Z1 expects: their previous phases drained mid-step t-1 -> safe
        if(tid==0){
            mbar_expect_(mbE,4096); mbar_expect_(mbZ,4096); mbar_expect_(mbZ1,4096);
        }

        // ---- LDG prefetches (independent of h; cover H-exchange tail) ----
        float exv0=0.f,exv1=0.f,eps0=0.f,eps1=0.f;
        if(tid<64){
            int col=tid&15, rp=tid>>4;
            size_t b0 = ((size_t)(cid*8+2*rp  )*Tt + t)*128 + rank*16 + col;
            size_t b1 = ((size_t)(cid*8+2*rp+1)*Tt + t)*128 + rank*16 + col;
            exv0=g_Ex[b0]; exv1=g_Ex[b1]; eps0=eps[b0]; eps1=eps[b1];
        }
        float gxv[8];
        if(tid<128){
            int j=tid&31, rp=tid>>5;
            size_t gb0 = ((size_t)(cid*8+2*rp  )*Tt + t)*1024 + rank*32 + j;
            size_t gb1 = ((size_t)(cid*8+2*rp+1)*Tt + t)*1024 + rank*32 + j;
            #pragma unroll
            for(int g=0;g<4;g++){ gxv[g]=g_Gx[gb0+(size_t)g*256]; gxv[4+g]=g_Gx[gb1+(size_t)g*256]; }
        }

        // ---- H: wait for previous step's exchange, THEN post this step's expect
        if(t>0) mbar_wait_(mbH, (t-1)&1);
        if(tid==0) mbar_expect_(mbH,8192);

        // store h input for prior/dec epilogues
        if(tid<256){
            int row=tid>>5, j=tid&31;
            g_h[((size_t)t*128 + cid*8 + row)*256 + rank*32 + j] = hTc[(rank*32+j)*8 + row];
        }

        // ---- (a) enc_h slice: relu(Ex + h @ Wenc_h) ----
        {
            int oc=tid&127, seg=tid>>7, row=oc>>4, col=oc&15;
            float s0=0.f, s1=0.f;
            int k0=seg*64;
            #pragma unroll 4
            for(int k=k0;k<k0+64;k+=2){
                s0 = fmaf(hTc[k*8+row],     Wenc_s[k*16+col],     s0);
                s1 = fmaf(hTc[(k+1)*8+row], Wenc_s[(k+1)*16+col], s1);
            }
            ap[tid]=s0+s1;
        }
        __syncthreads();
        if(tid<64){
            int col=tid&15, rp=tid>>4, r0=2*rp, r1=r0+1;
            int i0=r0*16+col, i1=r1*16+col;
            float v0 = ap[i0]+ap[i0+128]+ap[i0+256]+ap[i0+384] + exv0;
            float v1 = ap[i1]+ap[i1+128]+ap[i1+256]+ap[i1+384] + exv1;
            stgA[col*8+r0]=fmaxf(v0,0.f);
            stgA[col*8+r1]=fmaxf(v1,0.f);
        }
        __syncthreads();
        if(tid<8){
            fence_async_();
            blkcp_(mapa_(laE,(unsigned)tid), srcA, 512u, mapa_(mbE,(unsigned)tid));
        }
        // d1 chunk A: h@R overlaps E exchange
        ull a0=0ull,a1=0ull,a2=0ull,a3=0ull;
        {
            const int kr0=dseg*64;
            #pragma unroll
            for(int kk=kr0;kk<kr0+22;kk++){
                ull w2 = pack2_(R_s[kk*128+dcol]);
                const ulonglong2* hp = (const ulonglong2*)(hTc + kk*8);
                ulonglong2 p0 = hp[0], p1 = hp[1];
                ffma2_(a0,w2,p0.x); ffma2_(a1,w2,p0.y);
                ffma2_(a2,w2,p1.x); ffma2_(a3,w2,p1.y);
            }
        }
        mbar_wait_(mbE, par);

        // ---- (b) enc_mu / enc_sigma / z ----
        {
            int o=tid&255, seg=tid>>8, row=o>>5, col=(o>>1)&15, typ=o&1;
            const float* W = typ ? Wsg_s : Wmu_s;
            float s0=0.f, s1=0.f;
            int k0=seg*64;
            #pragma unroll 4
            for(int k=k0;k<k0+64;k+=2){
                s0 = fmaf(eT[k*8+row],     W[k*16+col],     s0);
                s1 = fmaf(eT[(k+1)*8+row], W[(k+1)*16+col], s1);
            }
            ap[tid]=s0+s1;
        }
        __syncthreads();
        if(tid<64){
            int col=tid&15, rp=tid>>4, r0=2*rp, r1=r0+1;
            int o0=(r0<<5)+(col<<1), o1=(r1<<5)+(col<<1);
            float mu0 = ap[o0]   + ap[o0+256]   + bias_s[col];
            float sg0 = softplus_(ap[o0+1] + ap[o0+257] + bias_s[16+col]);
            float mu1 = ap[o1]   + ap[o1+256]   + bias_s[col];
            float sg1 = softplus_(ap[o1+1] + ap[o1+257] + bias_s[16+col]);
            size_t b0 = ((size_t)(cid*8+r0)*Tt + t)*128 + rank*16 + col;
            size_t b1 = ((size_t)(cid*8+r1)*Tt + t)*128 + rank*16 + col;
            out[OFF_EMU+b0]=mu0; out[OFF_ESG+b0]=sg0;
            out[OFF_EMU+b1]=mu1; out[OFF_ESG+b1]=sg1;
            stgZ[col*8+r0]=fmaf(sg0, eps0, mu0);
            stgZ[col*8+r1]=fmaf(sg1, eps1, mu1);
        }
        __syncthreads();
        if(tid<8){
            fence_async_();
            blkcp_(mapa_(laZ,(unsigned)tid), srcZ, 512u, mapa_(mbZ,(unsigned)tid));
        }
        // d1 chunk B: overlaps Z exchange
        {
            const int kr0=dseg*64;
            #pragma unroll
            for(int kk=kr0+22;kk<kr0+43;kk++){
                ull w2 = pack2_(R_s[kk*128+dcol]);
                const ulonglong2* hp = (const ulonglong2*)(hTc + kk*8);
                ulonglong2 p0 = hp[0], p1 = hp[1];
                ffma2_(a0,w2,p0.x); ffma2_(a1,w2,p0.y);
                ffma2_(a2,w2,p1.x); ffma2_(a3,w2,p1.y);
            }
        }
        mbar_wait_(mbZ, par);

        // ---- (c) z1 = relu(z @ phi_z_w + b) ----
        {
            int oc=tid&127, seg=tid>>7, row=oc>>4, col=oc&15;
            float s0=0.f, s1=0.f;
            int k0=seg*32;
            #pragma unroll 4
            for(int k=k0;k<k0+32;k+=2){
                s0 = fmaf(zT[k*8+row],     Wpz_s[k*16+col],     s0);
                s1 = fmaf(zT[(k+1)*8+row], Wpz_s[(k+1)*16+col], s1);
            }
            ap[tid]=s0+s1;
        }
        __syncthreads();
        if(tid<64){
            int col=tid&15, rp=tid>>4, r0=2*rp, r1=r0+1;
            int i0=r0*16+col, i1=r1*16+col;
            float v0 = ap[i0]+ap[i0+128]+ap[i0+256]+ap[i0+384] + bias_s[32+col];
            float v1 = ap[i1]+ap[i1+128]+ap[i1+256]+ap[i1+384] + bias_s[32+col];
            v0=fmaxf(v0,0.f); v1=fmaxf(v1,0.f);
            g_z1[((size_t)t*128 + cid*8 + r0)*128 + rank*16 + col] = v0;
            g_z1[((size_t)t*128 + cid*8 + r1)*128 + rank*16 + col] = v1;
            if(t==Tt-1){
                out[(size_t)(cid*8+r0)*128 + rank*16 + col] = v0;
                out[(size_t)(cid*8+r1)*128 + rank*16 + col] = v1;
            }
            stgZ1[col*8+r0]=v0;
            stgZ1[col*8+r1]=v1;
        }
        __syncthreads();
        if(tid<8){
            fence_async_();
            blkcp_(mapa_(laZ1,(unsigned)tid), srcZ1, 512u, mapa_(mbZ1,(unsigned)tid));
        }
        // Kz register prefetch (LDG latency) + d1 chunk C overlap Z1 exchange
        float w32[32];
        {
            const float4* kp4 = (const float4*)g_Kp;
            #pragma unroll
            for(int u=0;u<8;u++) *(float4*)&w32[u*4] = __ldg(&kp4[(rank*8+u)*512 + tid]);
        }
        {
            const int kr0=dseg*64;
            #pragma unroll
            for(int kk=kr0+43;kk<kr0+64;kk++){
                ull w2 = pack2_(R_s[kk*128+dcol]);
                const ulonglong2* hp = (const ulonglong2*)(hTc + kk*8);
                ulonglong2 p0 = hp[0], p1 = hp[1];
                ffma2_(a0,w2,p0.x); ffma2_(a1,w2,p0.y);
                ffma2_(a2,w2,p1.x); ffma2_(a3,w2,p1.y);
            }
        }
        mbar_wait_(mbZ1, par);

        // ---- (d2) z1@Kz from registers ----
        {
            const int kz0=dseg*32;
            #pragma unroll
            for(int u=0;u<32;u++){
                ull w2 = pack2_(w32[u]);
                const ulonglong2* zp = (const ulonglong2*)(z1T + (kz0+u)*8);
                ulonglong2 p0 = zp[0], p1 = zp[1];
                ffma2_(a0,w2,p0.x); ffma2_(a1,w2,p0.y);
                ffma2_(a2,w2,p1.x); ffma2_(a3,w2,p1.y);
            }
            float r0,r1,r2,r3,r4,r5,r6,r7;
            unpack2_(a0,r0,r1); unpack2_(a1,r2,r3);
            unpack2_(a2,r4,r5); unpack2_(a3,r6,r7);
            float* gpp = gp + dseg*1024 + dcol;
            gpp[0*128]=r0; gpp[1*128]=r1; gpp[2*128]=r2; gpp[3*128]=r3;
            gpp[4*128]=r4; gpp[5*128]=r5; gpp[6*128]=r6; gpp[7*128]=r7;
        }
        __syncthreads();
        if(tid<128){
            int j=tid&31, rp=tid>>5, r0=2*rp, r1=r0+1;
            float gi0=gxv[0], gf0=gxv[1], gg0=gxv[2], go0=gxv[3];
            float gi1=gxv[4], gf1=gxv[5], gg1=gxv[6], go1=gxv[7];
            #pragma unroll
            for(int s=0;s<4;s++){
                const float* p0 = gp + s*1024 + r0*128;
                const float* p1 = gp + s*1024 + r1*128;
                gi0+=p0[j]; gf0+=p0[32+j]; gg0+=p0[64+j]; go0+=p0[96+j];
                gi1+=p1[j]; gf1+=p1[32+j]; gg1+=p1[64+j]; go1+=p1[96+j];
            }
            float iv0=sigmoid_(gi0), fv0=sigmoid_(gf0), gv0=tanhf(gg0), ov0=sigmoid_(go0);
            float iv1=sigmoid_(gi1), fv1=sigmoid_(gf1), gv1=tanhf(gg1), ov1=sigmoid_(go1);
            c0_st = fv0*c0_st + iv0*gv0;
            c1_st = fv1*c1_st + iv1*gv1;
            stgH[j*8+r0] = ov0*tanhf(c0_st);
            stgH[j*8+r1] = ov1*tanhf(c1_st);
        }
        __syncthreads();
        if(tid<8){
            fence_async_();
            unsigned laH = smb + (hTn_off + (unsigned)rank*256u)*4u;
            blkcp_(mapa_(laH,(unsigned)tid), srcH, 1024u, mapa_(mbH,(unsigned)tid));
        }
        // no waitH here: it moved to the top of the next iteration
    }
    mbar_wait_(mbH, (Tt-1)&1);   // drain last h exchange before exit
    CLUSTER_SYNC_();
}

extern "C" void kernel_launch(void* const* d_in, const int* in_sizes, int n_in,
                              void* d_out, int out_size)
{
    (void)in_sizes;(void)n_in;(void)out_size;
    const float* x           =(const float*)d_in[0];
    const float* eps         =(const float*)d_in[1];
    const float* prior_h_w   =(const float*)d_in[2];
    const float* prior_h_b   =(const float*)d_in[3];
    const float* prior_mu_w  =(const float*)d_in[4];
    const float* prior_mu_b  =(const float*)d_in[5];
    const float* prior_sg_w  =(const float*)d_in[6];
    const float* prior_sg_b  =(const float*)d_in[7];
    const float* phi_x_w     =(const float*)d_in[8];
    const float* phi_x_b     =(const float*)d_in[9];
    const float* enc_h_w     =(const float*)d_in[10];
    const float* enc_h_b     =(const float*)d_in[11];
    const float* enc_mu_w    =(const float*)d_in[12];
    const float* enc_mu_b    =(const float*)d_in[13];
    const float* enc_sg_w    =(const float*)d_in[14];
    const float* enc_sg_b    =(const float*)d_in[15];
    const float* phi_z_w     =(const float*)d_in[16];
    const float* phi_z_b     =(const float*)d_in[17];
    const float* dec_h_w     =(const float*)d_in[18];
    const float* dec_h_b     =(const float*)d_in[19];
    const float* dec_mu_w    =(const float*)d_in[20];
    const float* dec_mu_b    =(const float*)d_in[21];
    const float* dec_sg_w    =(const float*)d_in[22];
    const float* dec_sg_b    =(const float*)d_in[23];
    const float* lstm_kernel =(const float*)d_in[24];
    const float* lstm_rec    =(const float*)d_in[25];
    const float* lstm_bias   =(const float*)d_in[26];
    float* out=(float*)d_out;

    float *pH,*pZ1,*pPH,*pDH;
    cudaGetSymbolAddress((void**)&pH,  g_h);
    cudaGetSymbolAddress((void**)&pZ1, g_z1);
    cudaGetSymbolAddress((void**)&pPH, g_PH);
    cudaGetSymbolAddress((void**)&pDH, g_DH);

    cudaFuncSetAttribute(seq_clu, cudaFuncAttributeMaxDynamicSharedMemorySize, SEQ_SMEM_BYTES);

    // 1. prep (bias folds + coalesced Kz)
    prep_k<<<517,256>>>(lstm_kernel,lstm_bias,enc_h_w,enc_h_b,phi_x_b);
    // 2. fused weights
    wk_k<<<576,256>>>(phi_x_w,lstm_kernel,enc_h_w);
    // 3. fused big input GEMMs
    inputs_k<<<dim3(18,512),256>>>(x);
    // 4. sequential recurrence (launch #4 -> captured by ncu)
    seq_clu<<<128,512,SEQ_SMEM_BYTES>>>(eps, enc_h_w, enc_mu_w,enc_mu_b, enc_sg_w,enc_sg_b,
                                        phi_z_w,phi_z_b, lstm_rec, out);
    // 5-10. epilogues
    gemm_k<<<dim3(2,512),256>>>(pH,256,256, nullptr,0,0, prior_h_w,128, nullptr,0,
                                prior_h_b, pPH,128,1,0);
    gemm_k<<<dim3(2,512),256>>>(pPH,128,128, nullptr,0,0, prior_mu_w,128, nullptr,0,
                                prior_mu_b, out+OFF_PMU,128,0,1);
    gemm_k<<<dim3(2,512),256>>>(pPH,128,128, nullptr,0,0, prior_sg_w,128, nullptr,0,
                                prior_sg_b, out+OFF_PSG,128,2,1);
    gemm_k<<<dim3(2,512),256>>>(pZ1,128,128, pH,256,256, dec_h_w,128, dec_h_w+128*128,128,
                                dec_h_b, pDH,128,1,0);
    gemm_k<<<dim3(2,512),256>>>(pDH,128,128, nullptr,0,0, dec_mu_w,128, nullptr,0,
                                dec_mu_b, out+OFF_DMU,128,0,1);
    gemm_k<<<dim3(2,512),256>>>(pDH,128,128, nullptr,0,0, dec_sg_w,128, nullptr,0,
                                dec_sg_b, out+OFF_DSG,128,2,1);
}

// round 14
// speedup vs baseline: 1.4511x; 1.1208x over previous
#include <cuda_runtime.h>
#include <stdint.h>
#include <math.h>

#define Tt 512
#define SEQSZ (128*512*128)
#define OFF_EMU 16384
#define OFF_ESG (OFF_EMU + 1*SEQSZ)
#define OFF_DMU (OFF_EMU + 2*SEQSZ)
#define OFF_DSG (OFF_EMU + 3*SEQSZ)
#define OFF_PMU (OFF_EMU + 4*SEQSZ)
#define OFF_PSG (OFF_EMU + 5*SEQSZ)

// scratch (static device globals; no runtime alloc)
__device__ float g_Gx[65536*1024];
__device__ float g_Ex[65536*128];
__device__ float g_h [65536*256];
__device__ float g_z1[65536*128];
__device__ float g_PH[65536*128];
__device__ float g_DH[65536*128];
__device__ float g_Wgx[128*1024];
__device__ float g_Wex[128*128];
__device__ float g_Kp[8*8*512*4];
__device__ float g_gb[1024];
__device__ float g_eb[128];

typedef unsigned long long ull;

__device__ __forceinline__ float softplus_(float x){ return fmaxf(x,0.f)+log1pf(expf(-fabsf(x))); }
__device__ __forceinline__ float sigmoid_(float x){ return 1.f/(1.f+expf(-x)); }

__device__ __forceinline__ ull pack2_(float v){
    ull r; asm("mov.b64 %0, {%1, %1};" : "=l"(r) : "f"(v)); return r;
}
__device__ __forceinline__ void ffma2_(ull &d, ull a, ull b){
    asm("fma.rn.f32x2 %0, %1, %2, %0;" : "+l"(d) : "l"(a), "l"(b));
}
__device__ __forceinline__ void unpack2_(ull v, float &lo, float &hi){
    asm("mov.b64 {%0, %1}, %2;" : "=f"(lo), "=f"(hi) : "l"(v));
}
__device__ __forceinline__ unsigned mapa_(unsigned addr, unsigned rank){
    unsigned r; asm("mapa.shared::cluster.u32 %0, %1, %2;" : "=r"(r) : "r"(addr), "r"(rank));
    return r;
}
__device__ __forceinline__ void blkcp_(unsigned dst, unsigned src, unsigned bytes, unsigned mbar){
    asm volatile("cp.async.bulk.shared::cluster.shared::cta.mbarrier::complete_tx::bytes [%0], [%1], %2, [%3];"
        :: "r"(dst), "r"(src), "r"(bytes), "r"(mbar) : "memory");
}
__device__ __forceinline__ void fence_async_(){
    asm volatile("fence.proxy.async.shared::cta;" ::: "memory");
}
__device__ __forceinline__ void mbar_init_(unsigned mbar, unsigned cnt){
    asm volatile("mbarrier.init.shared.b64 [%0], %1;" :: "r"(mbar), "r"(cnt) : "memory");
}
__device__ __forceinline__ void mbar_expect_(unsigned mbar, unsigned bytes){
    asm volatile("mbarrier.arrive.expect_tx.shared.b64 _, [%0], %1;" :: "r"(mbar), "r"(bytes) : "memory");
}
__device__ __forceinline__ void mbar_wait_(unsigned mbar, unsigned parity){
    unsigned done;
    asm volatile("{\n\t.reg .pred p;\n\t"
        "mbarrier.try_wait.parity.acquire.cta.shared::cta.b64 p, [%1], %2;\n\t"
        "selp.b32 %0, 1, 0, p;\n\t}"
        : "=r"(done) : "r"(mbar), "r"(parity) : "memory");
    while(!done){
        asm volatile("{\n\t.reg .pred p;\n\t"
            "mbarrier.try_wait.parity.acquire.cta.shared::cta.b64 p, [%1], %2, 0x989680;\n\t"
            "selp.b32 %0, 1, 0, p;\n\t}"
            : "=r"(done) : "r"(mbar), "r"(parity) : "memory");
    }
}
#define CLUSTER_SYNC_() do{ \
    asm volatile("barrier.cluster.arrive.aligned;" ::: "memory"); \
    asm volatile("barrier.cluster.wait.aligned;" ::: "memory"); }while(0)

// ------------------------- tiled SGEMM (epilogues) -------------------------
__global__ __launch_bounds__(256) void gemm_k(
    const float* __restrict__ A1,int lda1,int K1,
    const float* __restrict__ A2,int lda2,int K2,
    const float* __restrict__ W1,int ldw1,
    const float* __restrict__ W2,int ldw2,
    const float* __restrict__ bias,
    float* __restrict__ out,int N,int act,int btmode)
{
    __shared__ __align__(16) float As[8][128];
    __shared__ __align__(16) float Ws[8][64];
    const int bm=blockIdx.y*128, bn=blockIdx.x*64;
    const int tid=threadIdx.x;
    const int ty=tid>>4, tx=tid&15;
    const int lr=tid>>1, lc=(tid&1)*4;
    const int wr=tid>>6, wc=tid&63;
    float acc[8][4];
    #pragma unroll
    for(int i=0;i<8;i++)
      #pragma unroll
      for(int j=0;j<4;j++) acc[i][j]=0.f;
    for(int seg=0;seg<2;seg++){
        const float* A = seg? A2:A1;
        if(A==nullptr) continue;
        const float* W = seg? W2:W1;
        const int lda=seg?lda2:lda1, ldw=seg?ldw2:ldw1, K=seg?K2:K1;
        for(int k0=0;k0<K;k0+=8){
            float4 av = *(const float4*)(A + (size_t)(bm+lr)*lda + k0+lc);
            float w0 = W[(size_t)(k0+wr)*ldw + bn+wc];
            float w1 = W[(size_t)(k0+wr+4)*ldw + bn+wc];
            __syncthreads();
            As[lc+0][lr]=av.x; As[lc+1][lr]=av.y; As[lc+2][lr]=av.z; As[lc+3][lr]=av.w;
            Ws[wr][wc]=w0; Ws[wr+4][wc]=w1;
            __syncthreads();
            #pragma unroll
            for(int kk=0;kk<8;kk++){
                float a[8],w[4];
                *(float4*)&a[0]=*(const float4*)&As[kk][ty*8];
                *(float4*)&a[4]=*(const float4*)&As[kk][ty*8+4];
                *(float4*)&w[0]=*(const float4*)&Ws[kk][tx*4];
                #pragma unroll
                for(int i=0;i<8;i++)
                  #pragma unroll
                  for(int j=0;j<4;j++) acc[i][j]=fmaf(a[i],w[j],acc[i][j]);
            }
        }
    }
    #pragma unroll
    for(int i=0;i<8;i++){
        int r=bm+ty*8+i;
        #pragma unroll
        for(int j=0;j<4;j++){
            int n=bn+tx*4+j;
            float v=acc[i][j];
            if(bias) v+=bias[n];
            if(act==1) v=fmaxf(v,0.f);
            else if(act==2) v=softplus_(v);
            size_t idx;
            if(btmode){ int b=r&127, t=r>>7; idx=((size_t)b*Tt+t)*(size_t)N+n; }
            else idx=(size_t)r*N+n;
            out[idx]=v;
        }
    }
}

// prep: Kz permuted-coalesced copy + bias folds
__global__ __launch_bounds__(256) void prep_k(
    const float* __restrict__ lstm_kernel,
    const float* __restrict__ lstm_bias,
    const float* __restrict__ enc_h_w,
    const float* __restrict__ enc_h_b,
    const float* __restrict__ phi_x_b)
{
    if(blockIdx.x < 512){
        int idx = blockIdx.x*256 + threadIdx.x;
        int e=idx&3, tid=(idx>>2)&511, u=(idx>>11)&7, rank=idx>>14;
        int dcol=tid&127, dseg=tid>>7;
        int gcol=(dcol>>5)*256 + rank*32 + (dcol&31);
        int k=dseg*32 + u*4 + e;
        g_Kp[idx] = lstm_kernel[(size_t)(128+k)*1024 + gcol];
    } else {
        int jj = (blockIdx.x-512)*256 + threadIdx.x;
        if(jj<1024){
            float s=lstm_bias[jj];
            for(int f=0;f<128;f++) s=fmaf(phi_x_b[f],lstm_kernel[f*1024+jj],s);
            g_gb[jj]=s;
        } else if(jj<1152){
            int j=jj-1024;
            float s=enc_h_b[j];
            for(int f=0;f<128;f++) s=fmaf(phi_x_b[f],enc_h_w[f*128+j],s);
            g_eb[j]=s;
        }
    }
}

// wk: fused weights Wgx = phi_x_w @ Kx ; Wex = phi_x_w @ Wenc_x
__global__ __launch_bounds__(256) void wk_k(
    const float* __restrict__ phi_x_w,
    const float* __restrict__ lstm_kernel,
    const float* __restrict__ enc_h_w)
{
    int idx = blockIdx.x*256 + threadIdx.x;
    if(idx < 131072){
        int i=idx>>10, c=idx&1023;
        float s=0.f;
        for(int m=0;m<128;m++) s=fmaf(phi_x_w[i*128+m], lstm_kernel[(size_t)m*1024+c], s);
        g_Wgx[idx]=s;
    } else {
        int j=idx-131072;
        int i=j>>7, c=j&127;
        float s=0.f;
        for(int m=0;m<128;m++) s=fmaf(phi_x_w[i*128+m], enc_h_w[m*128+c], s);
        g_Wex[j]=s;
    }
}

// fused input GEMMs: bx<16 -> Gx (N=1024), bx>=16 -> Ex (N=128)
__global__ __launch_bounds__(256) void inputs_k(const float* __restrict__ x)
{
    __shared__ __align__(16) float As[8][128];
    __shared__ __align__(16) float Ws[8][64];
    const int isGx = (blockIdx.x < 16);
    const float* W  = isGx ? g_Wgx : g_Wex;
    const float* bs = isGx ? g_gb  : g_eb;
    float* out      = isGx ? g_Gx  : g_Ex;
    const int ldw   = isGx ? 1024 : 128;
    const int N     = ldw;
    const int bn    = (isGx ? blockIdx.x : (blockIdx.x-16))*64;
    const int bm=blockIdx.y*128;
    const int tid=threadIdx.x;
    const int ty=tid>>4, tx=tid&15;
    const int lr=tid>>1, lc=(tid&1)*4;
    const int wr=tid>>6, wc=tid&63;
    float acc[8][4];
    #pragma unroll
    for(int i=0;i<8;i++)
      #pragma unroll
      for(int j=0;j<4;j++) acc[i][j]=0.f;
    for(int k0=0;k0<128;k0+=8){
        float4 av = *(const float4*)(x + (size_t)(bm+lr)*128 + k0+lc);
        float w0 = W[(size_t)(k0+wr)*ldw + bn+wc];
        float w1 = W[(size_t)(k0+wr+4)*ldw + bn+wc];
        __syncthreads();
        As[lc+0][lr]=av.x; As[lc+1][lr]=av.y; As[lc+2][lr]=av.z; As[lc+3][lr]=av.w;
        Ws[wr][wc]=w0; Ws[wr+4][wc]=w1;
        __syncthreads();
        #pragma unroll
        for(int kk=0;kk<8;kk++){
            float a[8],w[4];
            *(float4*)&a[0]=*(const float4*)&As[kk][ty*8];
            *(float4*)&a[4]=*(const float4*)&As[kk][ty*8+4];
            *(float4*)&w[0]=*(const float4*)&Ws[kk][tx*4];
            #pragma unroll
            for(int i=0;i<8;i++)
              #pragma unroll
              for(int j=0;j<4;j++) acc[i][j]=fmaf(a[i],w[j],acc[i][j]);
        }
    }
    #pragma unroll
    for(int i=0;i<8;i++){
        int r=bm+ty*8+i;
        #pragma unroll
        for(int j=0;j<4;j++){
            int n=bn+tx*4+j;
            out[(size_t)r*N+n]=acc[i][j]+bs[n];
        }
    }
}

// ---------------- cluster-distributed sequential recurrence ----------------
// R11 structure; phases a/b restructured to ffma2 pair-loads (fewer LDS slots).
#define S_R    0
#define S_WE   32768
#define S_WMS  36864    // interleaved [k][col][2] = (mu,sg), 4096 floats
#define S_WPZ  40960
#define S_HT   43008
#define S_ET   47104
#define S_ZT   48128
#define S_Z1T  49152
#define S_GP   50176
#define S_APX  54272    // paired partials, 1024 floats
#define S_BIAS 55296
#define S_MB   55344
#define S_STA  55352
#define S_STZ  55480
#define S_STZ1 55608
#define S_STH  55736
#define S_TOTF 55992
#define SEQ_SMEM_BYTES (S_TOTF*4)

__global__ void __cluster_dims__(8,1,1) __launch_bounds__(512,1) seq_clu(
    const float* __restrict__ eps,
    const float* __restrict__ enc_h_w,
    const float* __restrict__ enc_mu_w, const float* __restrict__ enc_mu_b,
    const float* __restrict__ enc_sg_w, const float* __restrict__ enc_sg_b,
    const float* __restrict__ phi_z_w,  const float* __restrict__ phi_z_b,
    const float* __restrict__ lstm_rec,
    float* __restrict__ out)
{
    extern __shared__ __align__(16) float sm[];
    float* R_s    = sm + S_R;
    float* Wenc_s = sm + S_WE;
    float* Wms_s  = sm + S_WMS;
    float* Wpz_s  = sm + S_WPZ;
    float* hT     = sm + S_HT;
    float* eT     = sm + S_ET;
    float* zT     = sm + S_ZT;
    float* z1T    = sm + S_Z1T;
    float* gp     = sm + S_GP;
    float* apX    = sm + S_APX;
    float* bias_s = sm + S_BIAS;
    float* stgA   = sm + S_STA;
    float* stgZ   = sm + S_STZ;
    float* stgZ1  = sm + S_STZ1;
    float* stgH   = sm + S_STH;

    const unsigned smb = (unsigned)__cvta_generic_to_shared(sm);
    const unsigned mbE  = smb + S_MB*4;
    const unsigned mbZ  = mbE + 8;
    const unsigned mbZ1 = mbE + 16;
    const unsigned mbH  = mbE + 24;

    const int tid  = threadIdx.x;
    const int rank = blockIdx.x & 7;
    const int cid  = blockIdx.x >> 3;

    for(int idx=tid; idx<256*128; idx+=512){
        int k=idx>>7, c=idx&127;
        int gcol=(c>>5)*256 + rank*32 + (c&31);
        R_s[idx] = lstm_rec[k*1024 + gcol];
    }
    for(int idx=tid; idx<256*16; idx+=512){
        int k=idx>>4, j=idx&15;
        Wenc_s[idx] = enc_h_w[(128+k)*128 + rank*16 + j];
    }
    for(int idx=tid; idx<128*16; idx+=512){
        int k=idx>>4, j=idx&15;
        Wms_s[idx*2]   = enc_mu_w[k*128 + rank*16 + j];
        Wms_s[idx*2+1] = enc_sg_w[k*128 + rank*16 + j];
    }
    for(int idx=tid; idx<128*16; idx+=512){
        int k=idx>>4, j=idx&15;
        Wpz_s[idx] = phi_z_w [k*128 + rank*16 + j];
    }
    if(tid<16){
        bias_s[tid]    = enc_mu_b[rank*16+tid];
        bias_s[16+tid] = enc_sg_b[rank*16+tid];
        bias_s[32+tid] = phi_z_b [rank*16+tid];
    }
    for(int idx=tid; idx<2*256*8; idx+=512) hT[idx]=0.f;
    if(tid==0){
        mbar_init_(mbE,1); mbar_init_(mbZ,1); mbar_init_(mbZ1,1); mbar_init_(mbH,1);
    }
    __syncthreads();
    CLUSTER_SYNC_();

    float c0_st = 0.f, c1_st = 0.f;

    const int dcol = tid & 127, dseg = tid >> 7;
    const unsigned laE  = smb + (unsigned)S_ET*4u  + (unsigned)rank*512u;
    const unsigned laZ  = smb + (unsigned)S_ZT*4u  + (unsigned)rank*512u;
    const unsigned laZ1 = smb + (unsigned)S_Z1T*4u + (unsigned)rank*512u;
    const unsigned srcA  = smb + (unsigned)S_STA*4u;
    const unsigned srcZ  = smb + (unsigned)S_STZ*4u;
    const unsigned srcZ1 = smb + (unsigned)S_STZ1*4u;
    const unsigned srcH  = smb + (unsigned)S_STH*4u;

    for(int t=0; t<Tt; t++){
        const unsigned par = t & 1;
        float* hTc = hT + (t&1)*2048;
        const unsigned hTn_off = (unsigned)(S_HT + ((t+1)&1)*2048);

        // E/Z/Z1 expects: their previous phases drained mid-step t-1 -> safe
        if(tid==0){
            mbar_expect_(mbE,4096); mbar_expect_(mbZ,4096); mbar_expect_(mbZ1,4096);
        }

        // ---- LDG prefetches (independent of h; cover H-exchange tail) ----
        float exv=0.f, epsv=0.f;
        if(tid<128){
            int row=tid>>4, col=tid&15;
            size_t b = ((size_t)(cid*8+row)*Tt + t)*128 + rank*16 + col;
            exv=g_Ex[b]; epsv=eps[b];
        }
        float gxv[8];
        if(tid<128){
            int j=tid&31, rp=tid>>5;
            size_t gb0 = ((size_t)(cid*8+2*rp  )*Tt + t)*1024 + rank*32 + j;
            size_t gb1 = ((size_t)(cid*8+2*rp+1)*Tt + t)*1024 + rank*32 + j;
            #pragma unroll
            for(int g=0;g<4;g++){ gxv[g]=g_Gx[gb0+(size_t)g*256]; gxv[4+g]=g_Gx[gb1+(size_t)g*256]; }
        }

        // ---- H: wait for previous step's exchange, THEN post this step's expect
        if(t>0) mbar_wait_(mbH, (t-1)&1);
        if(tid==0) mbar_expect_(mbH,8192);

        // store h input for prior/dec epilogues
        if(tid<256){
            int row=tid>>5, j=tid&31;
            g_h[((size_t)t*128 + cid*8 + row)*256 + rank*32 + j] = hTc[(rank*32+j)*8 + row];
        }

        // ---- (a) enc_h: ffma2 over col-pairs, 8 k-segments ----
        {
            int cp=tid&7, row=(tid>>3)&7, seg=tid>>6;
            ull acc=0ull;
            const ull* wp2 = (const ull*)Wenc_s;
            int k0=seg*32;
            #pragma unroll 8
            for(int k=k0;k<k0+32;k++){
                ull w2 = wp2[k*8+cp];
                ull h2 = pack2_(hTc[k*8+row]);
                ffma2_(acc,h2,w2);
            }
            *(ull*)&apX[tid*2] = acc;
        }
        __syncthreads();
        if(tid<128){
            int row=tid>>4, col=tid&15, cp=col>>1, e=col&1;
            float v = exv;
            #pragma unroll
            for(int s=0;s<8;s++) v += apX[(s*64 + row*8 + cp)*2 + e];
            stgA[col*8+row]=fmaxf(v,0.f);
        }
        __syncthreads();
        if(tid<8){
            fence_async_();
            blkcp_(mapa_(laE,(unsigned)tid), srcA, 512u, mapa_(mbE,(unsigned)tid));
        }
        // d1 chunk A: h@R overlaps E exchange
        ull a0=0ull,a1=0ull,a2=0ull,a3=0ull;
        {
            const int kr0=dseg*64;
            #pragma unroll
            for(int kk=kr0;kk<kr0+22;kk++){
                ull w2 = pack2_(R_s[kk*128+dcol]);
                const ulonglong2* hp = (const ulonglong2*)(hTc + kk*8);
                ulonglong2 p0 = hp[0], p1 = hp[1];
                ffma2_(a0,w2,p0.x); ffma2_(a1,w2,p0.y);
                ffma2_(a2,w2,p1.x); ffma2_(a3,w2,p1.y);
            }
        }
        mbar_wait_(mbE, par);

        // ---- (b) enc_mu/enc_sigma as paired ffma2; z local ----
        {
            int col=tid&15, row=(tid>>4)&7, seg=tid>>7;
            ull acc=0ull;
            const ull* wp2 = (const ull*)Wms_s;
            int k0=seg*32;
            #pragma unroll 8
            for(int k=k0;k<k0+32;k++){
                ull w2 = wp2[k*16+col];
                ull e2 = pack2_(eT[k*8+row]);
                ffma2_(acc,e2,w2);
            }
            *(ull*)&apX[tid*2] = acc;
        }
        __syncthreads();
        if(tid<128){
            int row=tid>>4, col=tid&15;
            float mu=bias_s[col], sg=bias_s[16+col];
            #pragma unroll
            for(int s=0;s<4;s++){
                int o=(s*128 + row*16 + col)*2;
                mu += apX[o]; sg += apX[o+1];
            }
            sg = softplus_(sg);
            size_t b = ((size_t)(cid*8+row)*Tt + t)*128 + rank*16 + col;
            out[OFF_EMU+b]=mu; out[OFF_ESG+b]=sg;
            stgZ[col*8+row]=fmaf(sg, epsv, mu);
        }
        __syncthreads();
        if(tid<8){
            fence_async_();
            blkcp_(mapa_(laZ,(unsigned)tid), srcZ, 512u, mapa_(mbZ,(unsigned)tid));
        }
        // d1 chunk B: overlaps Z exchange
        {
            const int kr0=dseg*64;
            #pragma unroll
            for(int kk=kr0+22;kk<kr0+43;kk++){
                ull w2 = pack2_(R_s[kk*128+dcol]);
                const ulonglong2* hp = (const ulonglong2*)(hTc + kk*8);
                ulonglong2 p0 = hp[0], p1 = hp[1];
                ffma2_(a0,w2,p0.x); ffma2_(a1,w2,p0.y);
                ffma2_(a2,w2,p1.x); ffma2_(a3,w2,p1.y);
            }
        }
        mbar_wait_(mbZ, par);

        // ---- (c) z1 = relu(z @ phi_z_w + b) ----
        {
            int oc=tid&127, seg=tid>>7, row=oc>>4, col=oc&15;
            float s0=0.f, s1=0.f;
            int k0=seg*32;
            #pragma unroll 4
            for(int k=k0;k<k0+32;k+=2){
                s0 = fmaf(zT[k*8+row],     Wpz_s[k*16+col],     s0);
                s1 = fmaf(zT[(k+1)*8+row], Wpz_s[(k+1)*16+col], s1);
            }
            apX[tid]=s0+s1;
        }
        __syncthreads();
        if(tid<64){
            int col=tid&15, rp=tid>>4, r0=2*rp, r1=r0+1;
            int i0=r0*16+col, i1=r1*16+col;
            float v0 = apX[i0]+apX[i0+128]+apX[i0+256]+apX[i0+384] + bias_s[32+col];
            float v1 = apX[i1]+apX[i1+128]+apX[i1+256]+apX[i1+384] + bias_s[32+col];
            v0=fmaxf(v0,0.f); v1=fmaxf(v1,0.f);
            g_z1[((size_t)t*128 + cid*8 + r0)*128 + rank*16 + col] = v0;
            g_z1[((size_t)t*128 + cid*8 + r1)*128 + rank*16 + col] = v1;
            if(t==Tt-1){
                out[(size_t)(cid*8+r0)*128 + rank*16 + col] = v0;
                out[(size_t)(cid*8+r1)*128 + rank*16 + col] = v1;
            }
            stgZ1[col*8+r0]=v0;
            stgZ1[col*8+r1]=v1;
        }
        __syncthreads();
        if(tid<8){
            fence_async_();
            blkcp_(mapa_(laZ1,(unsigned)tid), srcZ1, 512u, mapa_(mbZ1,(unsigned)tid));
        }
        // Kz register prefetch + d1 chunk C overlap Z1 exchange
        float w32[32];
        {
            const float4* kp4 = (const float4*)g_Kp;
            #pragma unroll
            for(int u=0;u<8;u++) *(float4*)&w32[u*4] = __ldg(&kp4[(rank*8+u)*512 + tid]);
        }
        {
            const int kr0=dseg*64;
            #pragma unroll
            for(int kk=kr0+43;kk<kr0+64;kk++){
                ull w2 = pack2_(R_s[kk*128+dcol]);
                const ulonglong2* hp = (const ulonglong2*)(hTc + kk*8);
                ulonglong2 p0 = hp[0], p1 = hp[1];
                ffma2_(a0,w2,p0.x); ffma2_(a1,w2,p0.y);
                ffma2_(a2,w2,p1.x); ffma2_(a3,w2,p1.y);
            }
        }
        mbar_wait_(mbZ1, par);

        // ---- (d2) z1@Kz from registers ----
        {
            const int kz0=dseg*32;
            #pragma unroll
            for(int u=0;u<32;u++){
                ull w2 = pack2_(w32[u]);
                const ulonglong2* zp = (const ulonglong2*)(z1T + (kz0+u)*8);
                ulonglong2 p0 = zp[0], p1 = zp[1];
                ffma2_(a0,w2,p0.x); ffma2_(a1,w2,p0.y);
                ffma2_(a2,w2,p1.x); ffma2_(a3,w2,p1.y);
            }
            float r0,r1,r2,r3,r4,r5,r6,r7;
            unpack2_(a0,r0,r1); unpack2_(a1,r2,r3);
            unpack2_(a2,r4,r5); unpack2_(a3,r6,r7);
            float* gpp = gp + dseg*1024 + dcol;
            gpp[0*128]=r0; gpp[1*128]=r1; gpp[2*128]=r2; gpp[3*128]=r3;
            gpp[4*128]=r4; gpp[5*128]=r5; gpp[6*128]=r6; gpp[7*128]=r7;
        }
        __syncthreads();
        if(tid<128){
            int j=tid&31, rp=tid>>5, r0=2*rp, r1=r0+1;
            float gi0=gxv[0], gf0=gxv[1], gg0=gxv[2], go0=gxv[3];
            float gi1=gxv[4], gf1=gxv[5], gg1=gxv[6], go1=gxv[7];
            #pragma unroll
            for(int s=0;s<4;s++){
                const float* p0 = gp + s*1024 + r0*128;
                const float* p1 = gp + s*1024 + r1*128;
                gi0+=p0[j]; gf0+=p0[32+j]; gg0+=p0[64+j]; go0+=p0[96+j];
                gi1+=p1[j]; gf1+=p1[32+j]; gg1+=p1[64+j]; go1+=p1[96+j];
            }
            float iv0=sigmoid_(gi0), fv0=sigmoid_(gf0), gv0=tanhf(gg0), ov0=sigmoid_(go0);
            float iv1=sigmoid_(gi1), fv1=sigmoid_(gf1), gv1=tanhf(gg1), ov1=sigmoid_(go1);
            c0_st = fv0*c0_st + iv0*gv0;
            c1_st = fv1*c1_st + iv1*gv1;
            stgH[j*8+r0] = ov0*tanhf(c0_st);
            stgH[j*8+r1] = ov1*tanhf(c1_st);
        }
        __syncthreads();
        if(tid<8){
            fence_async_();
            unsigned laH = smb + (hTn_off + (unsigned)rank*256u)*4u;
            blkcp_(mapa_(laH,(unsigned)tid), srcH, 1024u, mapa_(mbH,(unsigned)tid));
        }
        // waitH at top of next iteration
    }
    mbar_wait_(mbH, (Tt-1)&1);
    CLUSTER_SYNC_();
}

extern "C" void kernel_launch(void* const* d_in, const int* in_sizes, int n_in,
                              void* d_out, int out_size)
{
    (void)in_sizes;(void)n_in;(void)out_size;
    const float* x           =(const float*)d_in[0];
    const float* eps         =(const float*)d_in[1];
    const float* prior_h_w   =(const float*)d_in[2];
    const float* prior_h_b   =(const float*)d_in[3];
    const float* prior_mu_w  =(const float*)d_in[4];
    const float* prior_mu_b  =(const float*)d_in[5];
    const float* prior_sg_w  =(const float*)d_in[6];
    const float* prior_sg_b  =(const float*)d_in[7];
    const float* phi_x_w     =(const float*)d_in[8];
    const float* phi_x_b     =(const float*)d_in[9];
    const float* enc_h_w     =(const float*)d_in[10];
    const float* enc_h_b     =(const float*)d_in[11];
    const float* enc_mu_w    =(const float*)d_in[12];
    const float* enc_mu_b    =(const float*)d_in[13];
    const float* enc_sg_w    =(const float*)d_in[14];
    const float* enc_sg_b    =(const float*)d_in[15];
    const float* phi_z_w     =(const float*)d_in[16];
    const float* phi_z_b     =(const float*)d_in[17];
    const float* dec_h_w     =(const float*)d_in[18];
    const float* dec_h_b     =(const float*)d_in[19];
    const float* dec_mu_w    =(const float*)d_in[20];
    const float* dec_mu_b    =(const float*)d_in[21];
    const float* dec_sg_w    =(const float*)d_in[22];
    const float* dec_sg_b    =(const float*)d_in[23];
    const float* lstm_kernel =(const float*)d_in[24];
    const float* lstm_rec    =(const float*)d_in[25];
    const float* lstm_bias   =(const float*)d_in[26];
    float* out=(float*)d_out;

    float *pH,*pZ1,*pPH,*pDH;
    cudaGetSymbolAddress((void**)&pH,  g_h);
    cudaGetSymbolAddress((void**)&pZ1, g_z1);
    cudaGetSymbolAddress((void**)&pPH, g_PH);
    cudaGetSymbolAddress((void**)&pDH, g_DH);

    cudaFuncSetAttribute(seq_clu, cudaFuncAttributeMaxDynamicSharedMemorySize, SEQ_SMEM_BYTES);

    // 1. prep (bias folds + coalesced Kz)
    prep_k<<<517,256>>>(lstm_kernel,lstm_bias,enc_h_w,enc_h_b,phi_x_b);
    // 2. fused weights
    wk_k<<<576,256>>>(phi_x_w,lstm_kernel,enc_h_w);
    // 3. fused big input GEMMs
    inputs_k<<<dim3(18,512),256>>>(x);
    // 4. sequential recurrence (launch #4 -> captured by ncu)
    seq_clu<<<128,512,SEQ_SMEM_BYTES>>>(eps, enc_h_w, enc_mu_w,enc_mu_b, enc_sg_w,enc_sg_b,
                                        phi_z_w,phi_z_b, lstm_rec, out);
    // 5-10. epilogues
    gemm_k<<<dim3(2,512),256>>>(pH,256,256, nullptr,0,0, prior_h_w,128, nullptr,0,
                                prior_h_b, pPH,128,1,0);
    gemm_k<<<dim3(2,512),256>>>(pPH,128,128, nullptr,0,0, prior_mu_w,128, nullptr,0,
                                prior_mu_b, out+OFF_PMU,128,0,1);
    gemm_k<<<dim3(2,512),256>>>(pPH,128,128, nullptr,0,0, prior_sg_w,128, nullptr,0,
                                prior_sg_b, out+OFF_PSG,128,2,1);
    gemm_k<<<dim3(2,512),256>>>(pZ1,128,128, pH,256,256, dec_h_w,128, dec_h_w+128*128,128,
                                dec_h_b, pDH,128,1,0);
    gemm_k<<<dim3(2,512),256>>>(pDH,128,128, nullptr,0,0, dec_mu_w,128, nullptr,0,
                                dec_mu_b, out+OFF_DMU,128,0,1);
    gemm_k<<<dim3(2,512),256>>>(pDH,128,128, nullptr,0,0, dec_sg_w,128, nullptr,0,
                                dec_sg_b, out+OFF_DSG,128,2,1);
}

// round 15
// speedup vs baseline: 1.4806x; 1.0203x over previous
#include <cuda_runtime.h>
#include <stdint.h>
#include <math.h>

#define Tt 512
#define SEQSZ (128*512*128)
#define OFF_EMU 16384
#define OFF_ESG (OFF_EMU + 1*SEQSZ)
#define OFF_DMU (OFF_EMU + 2*SEQSZ)
#define OFF_DSG (OFF_EMU + 3*SEQSZ)
#define OFF_PMU (OFF_EMU + 4*SEQSZ)
#define OFF_PSG (OFF_EMU + 5*SEQSZ)

// scratch (static device globals; no runtime alloc)
__device__ float g_Gx[65536*1024];   // PERMUTED: [b*T+t][rank*128 + j*4 + g]
__device__ float g_Ex[65536*128];
__device__ float g_h [65536*256];
__device__ float g_z1[65536*128];
__device__ float g_PH[65536*128];
__device__ float g_DH[65536*128];
__device__ float g_Wgx[128*1024];
__device__ float g_Wex[128*128];
__device__ float g_Kp[8*8*512*4];
__device__ float g_gb[1024];
__device__ float g_eb[128];

typedef unsigned long long ull;

__device__ __forceinline__ float softplus_(float x){ return fmaxf(x,0.f)+log1pf(expf(-fabsf(x))); }
__device__ __forceinline__ float sigmoid_(float x){ return 1.f/(1.f+expf(-x)); }

__device__ __forceinline__ ull pack2_(float v){
    ull r; asm("mov.b64 %0, {%1, %1};" : "=l"(r) : "f"(v)); return r;
}
__device__ __forceinline__ void ffma2_(ull &d, ull a, ull b){
    asm("fma.rn.f32x2 %0, %1, %2, %0;" : "+l"(d) : "l"(a), "l"(b));
}
__device__ __forceinline__ void unpack2_(ull v, float &lo, float &hi){
    asm("mov.b64 {%0, %1}, %2;" : "=f"(lo), "=f"(hi) : "l"(v));
}
__device__ __forceinline__ unsigned mapa_(unsigned addr, unsigned rank){
    unsigned r; asm("mapa.shared::cluster.u32 %0, %1, %2;" : "=r"(r) : "r"(addr), "r"(rank));
    return r;
}
__device__ __forceinline__ void blkcp_(unsigned dst, unsigned src, unsigned bytes, unsigned mbar){
    asm volatile("cp.async.bulk.shared::cluster.shared::cta.mbarrier::complete_tx::bytes [%0], [%1], %2, [%3];"
        :: "r"(dst), "r"(src), "r"(bytes), "r"(mbar) : "memory");
}
__device__ __forceinline__ void fence_async_(){
    asm volatile("fence.proxy.async.shared::cta;" ::: "memory");
}
__device__ __forceinline__ void mbar_init_(unsigned mbar, unsigned cnt){
    asm volatile("mbarrier.init.shared.b64 [%0], %1;" :: "r"(mbar), "r"(cnt) : "memory");
}
__device__ __forceinline__ void mbar_expect_(unsigned mbar, unsigned bytes){
    asm volatile("mbarrier.arrive.expect_tx.shared.b64 _, [%0], %1;" :: "r"(mbar), "r"(bytes) : "memory");
}
__device__ __forceinline__ void mbar_wait_(unsigned mbar, unsigned parity){
    unsigned done;
    asm volatile("{\n\t.reg .pred p;\n\t"
        "mbarrier.try_wait.parity.acquire.cta.shared::cta.b64 p, [%1], %2;\n\t"
        "selp.b32 %0, 1, 0, p;\n\t}"
        : "=r"(done) : "r"(mbar), "r"(parity) : "memory");
    while(!done){
        asm volatile("{\n\t.reg .pred p;\n\t"
            "mbarrier.try_wait.parity.acquire.cta.shared::cta.b64 p, [%1], %2, 0x989680;\n\t"
            "selp.b32 %0, 1, 0, p;\n\t}"
            : "=r"(done) : "r"(mbar), "r"(parity) : "memory");
    }
}
#define BARN_(id,n) asm volatile("bar.sync %0, %1;" :: "r"(id), "r"(n) : "memory")
#define CLUSTER_SYNC_() do{ \
    asm volatile("barrier.cluster.arrive.aligned;" ::: "memory"); \
    asm volatile("barrier.cluster.wait.aligned;" ::: "memory"); }while(0)

// ------------------------- tiled SGEMM (epilogues) -------------------------
__global__ __launch_bounds__(256) void gemm_k(
    const float* __restrict__ A1,int lda1,int K1,
    const float* __restrict__ A2,int lda2,int K2,
    const float* __restrict__ W1,int ldw1,
    const float* __restrict__ W2,int ldw2,
    const float* __restrict__ bias,
    float* __restrict__ out,int N,int act,int btmode)
{
    __shared__ __align__(16) float As[8][128];
    __shared__ __align__(16) float Ws[8][64];
    const int bm=blockIdx.y*128, bn=blockIdx.x*64;
    const int tid=threadIdx.x;
    const int ty=tid>>4, tx=tid&15;
    const int lr=tid>>1, lc=(tid&1)*4;
    const int wr=tid>>6, wc=tid&63;
    float acc[8][4];
    #pragma unroll
    for(int i=0;i<8;i++)
      #pragma unroll
      for(int j=0;j<4;j++) acc[i][j]=0.f;
    for(int seg=0;seg<2;seg++){
        const float* A = seg? A2:A1;
        if(A==nullptr) continue;
        const float* W = seg? W2:W1;
        const int lda=seg?lda2:lda1, ldw=seg?ldw2:ldw1, K=seg?K2:K1;
        for(int k0=0;k0<K;k0+=8){
            float4 av = *(const float4*)(A + (size_t)(bm+lr)*lda + k0+lc);
            float w0 = W[(size_t)(k0+wr)*ldw + bn+wc];
            float w1 = W[(size_t)(k0+wr+4)*ldw + bn+wc];
            __syncthreads();
            As[lc+0][lr]=av.x; As[lc+1][lr]=av.y; As[lc+2][lr]=av.z; As[lc+3][lr]=av.w;
            Ws[wr][wc]=w0; Ws[wr+4][wc]=w1;
            __syncthreads();
            #pragma unroll
            for(int kk=0;kk<8;kk++){
                float a[8],w[4];
                *(float4*)&a[0]=*(const float4*)&As[kk][ty*8];
                *(float4*)&a[4]=*(const float4*)&As[kk][ty*8+4];
                *(float4*)&w[0]=*(const float4*)&Ws[kk][tx*4];
                #pragma unroll
                for(int i=0;i<8;i++)
                  #pragma unroll
                  for(int j=0;j<4;j++) acc[i][j]=fmaf(a[i],w[j],acc[i][j]);
            }
        }
    }
    #pragma unroll
    for(int i=0;i<8;i++){
        int r=bm+ty*8+i;
        #pragma unroll
        for(int j=0;j<4;j++){
            int n=bn+tx*4+j;
            float v=acc[i][j];
            if(bias) v+=bias[n];
            if(act==1) v=fmaxf(v,0.f);
            else if(act==2) v=softplus_(v);
            size_t idx;
            if(btmode){ int b=r&127, t=r>>7; idx=((size_t)b*Tt+t)*(size_t)N+n; }
            else idx=(size_t)r*N+n;
            out[idx]=v;
        }
    }
}

// prep: Kz permuted-coalesced copy + bias folds
__global__ __launch_bounds__(256) void prep_k(
    const float* __restrict__ lstm_kernel,
    const float* __restrict__ lstm_bias,
    const float* __restrict__ enc_h_w,
    const float* __restrict__ enc_h_b,
    const float* __restrict__ phi_x_b)
{
    if(blockIdx.x < 512){
        int idx = blockIdx.x*256 + threadIdx.x;
        int e=idx&3, tid=(idx>>2)&511, u=(idx>>11)&7, rank=idx>>14;
        int dcol=tid&127, dseg=tid>>7;
        int gcol=(dcol>>5)*256 + rank*32 + (dcol&31);
        int k=dseg*32 + u*4 + e;
        g_Kp[idx] = lstm_kernel[(size_t)(128+k)*1024 + gcol];
    } else {
        int jj = (blockIdx.x-512)*256 + threadIdx.x;
        if(jj<1024){
            float s=lstm_bias[jj];
            for(int f=0;f<128;f++) s=fmaf(phi_x_b[f],lstm_kernel[f*1024+jj],s);
            g_gb[jj]=s;
        } else if(jj<1152){
            int j=jj-1024;
            float s=enc_h_b[j];
            for(int f=0;f<128;f++) s=fmaf(phi_x_b[f],enc_h_w[f*128+j],s);
            g_eb[j]=s;
        }
    }
}

// wk: fused weights Wgx = phi_x_w @ Kx ; Wex = phi_x_w @ Wenc_x
__global__ __launch_bounds__(256) void wk_k(
    const float* __restrict__ phi_x_w,
    const float* __restrict__ lstm_kernel,
    const float* __restrict__ enc_h_w)
{
    int idx = blockIdx.x*256 + threadIdx.x;
    if(idx < 131072){
        int i=idx>>10, c=idx&1023;
        float s=0.f;
        for(int m=0;m<128;m++) s=fmaf(phi_x_w[i*128+m], lstm_kernel[(size_t)m*1024+c], s);
        g_Wgx[idx]=s;
    } else {
        int j=idx-131072;
        int i=j>>7, c=j&127;
        float s=0.f;
        for(int m=0;m<128;m++) s=fmaf(phi_x_w[i*128+m], enc_h_w[m*128+c], s);
        g_Wex[j]=s;
    }
}

// fused input GEMMs: bx<16 -> Gx (N=1024, PERMUTED store), bx>=16 -> Ex
__global__ __launch_bounds__(256) void inputs_k(const float* __restrict__ x)
{
    __shared__ __align__(16) float As[8][128];
    __shared__ __align__(16) float Ws[8][64];
    const int isGx = (blockIdx.x < 16);
    const float* W  = isGx ? g_Wgx : g_Wex;
    const float* bs = isGx ? g_gb  : g_eb;
    float* out      = isGx ? g_Gx  : g_Ex;
    const int ldw   = isGx ? 1024 : 128;
    const int N     = ldw;
    const int bn    = (isGx ? blockIdx.x : (blockIdx.x-16))*64;
    const int bm=blockIdx.y*128;
    const int tid=threadIdx.x;
    const int ty=tid>>4, tx=tid&15;
    const int lr=tid>>1, lc=(tid&1)*4;
    const int wr=tid>>6, wc=tid&63;
    float acc[8][4];
    #pragma unroll
    for(int i=0;i<8;i++)
      #pragma unroll
      for(int j=0;j<4;j++) acc[i][j]=0.f;
    for(int k0=0;k0<128;k0+=8){
        float4 av = *(const float4*)(x + (size_t)(bm+lr)*128 + k0+lc);
        float w0 = W[(size_t)(k0+wr)*ldw + bn+wc];
        float w1 = W[(size_t)(k0+wr+4)*ldw + bn+wc];
        __syncthreads();
        As[lc+0][lr]=av.x; As[lc+1][lr]=av.y; As[lc+2][lr]=av.z; As[lc+3][lr]=av.w;
        Ws[wr][wc]=w0; Ws[wr+4][wc]=w1;
        __syncthreads();
        #pragma unroll
        for(int kk=0;kk<8;kk++){
            float a[8],w[4];
            *(float4*)&a[0]=*(const float4*)&As[kk][ty*8];
            *(float4*)&a[4]=*(const float4*)&As[kk][ty*8+4];
            *(float4*)&w[0]=*(const float4*)&Ws[kk][tx*4];
            #pragma unroll
            for(int i=0;i<8;i++)
              #pragma unroll
              for(int j=0;j<4;j++) acc[i][j]=fmaf(a[i],w[j],acc[i][j]);
        }
    }
    #pragma unroll
    for(int i=0;i<8;i++){
        int r=bm+ty*8+i;
        #pragma unroll
        for(int j=0;j<4;j++){
            int n=bn+tx*4+j;
            float v=acc[i][j]+bs[n];
            if(isGx){
                int g=n>>8, rem=n&255, rk=rem>>5, jj2=rem&31;
                out[(size_t)r*1024 + rk*128 + jj2*4 + g]=v;
            } else {
                out[(size_t)r*N+n]=v;
            }
        }
    }
}

// ---------------- cluster-distributed sequential recurrence ----------------
#define S_R    0
#define S_WE   32768
#define S_WMS  36864    // interleaved [k][col][2] = (mu,sg)
#define S_WPZ  40960
#define S_HT   43008
#define S_ET   47104
#define S_ZT   48128
#define S_Z1T  49152
#define S_GP   50176
#define S_APX  54272    // paired partials, 1024 floats
#define S_BIAS 55296
#define S_MB   55344
#define S_STA  55352
#define S_STZ  55480
#define S_STZ1 55608
#define S_STH  55736
#define S_TOTF 55992
#define SEQ_SMEM_BYTES (S_TOTF*4)

__global__ void __cluster_dims__(8,1,1) __launch_bounds__(512,1) seq_clu(
    const float* __restrict__ eps,
    const float* __restrict__ enc_h_w,
    const float* __restrict__ enc_mu_w, const float* __restrict__ enc_mu_b,
    const float* __restrict__ enc_sg_w, const float* __restrict__ enc_sg_b,
    const float* __restrict__ phi_z_w,  const float* __restrict__ phi_z_b,
    const float* __restrict__ lstm_rec,
    float* __restrict__ out)
{
    extern __shared__ __align__(16) float sm[];
    float* R_s    = sm + S_R;
    float* Wenc_s = sm + S_WE;
    float* Wms_s  = sm + S_WMS;
    float* Wpz_s  = sm + S_WPZ;
    float* hT     = sm + S_HT;
    float* eT     = sm + S_ET;
    float* zT     = sm + S_ZT;
    float* z1T    = sm + S_Z1T;
    float* gp     = sm + S_GP;
    float* apX    = sm + S_APX;
    float* bias_s = sm + S_BIAS;
    float* stgA   = sm + S_STA;
    float* stgZ   = sm + S_STZ;
    float* stgZ1  = sm + S_STZ1;
    float* stgH   = sm + S_STH;

    const unsigned smb = (unsigned)__cvta_generic_to_shared(sm);
    const unsigned mbE  = smb + S_MB*4;
    const unsigned mbZ  = mbE + 8;
    const unsigned mbZ1 = mbE + 16;
    const unsigned mbH  = mbE + 24;

    const int tid  = threadIdx.x;
    const int rank = blockIdx.x & 7;
    const int cid  = blockIdx.x >> 3;

    for(int idx=tid; idx<256*128; idx+=512){
        int k=idx>>7, c=idx&127;
        int gcol=(c>>5)*256 + rank*32 + (c&31);
        R_s[idx] = lstm_rec[k*1024 + gcol];
    }
    for(int idx=tid; idx<256*16; idx+=512){
        int k=idx>>4, j=idx&15;
        Wenc_s[idx] = enc_h_w[(128+k)*128 + rank*16 + j];
    }
    for(int idx=tid; idx<128*16; idx+=512){
        int k=idx>>4, j=idx&15;
        Wms_s[idx*2]   = enc_mu_w[k*128 + rank*16 + j];
        Wms_s[idx*2+1] = enc_sg_w[k*128 + rank*16 + j];
    }
    for(int idx=tid; idx<128*16; idx+=512){
        int k=idx>>4, j=idx&15;
        Wpz_s[idx] = phi_z_w [k*128 + rank*16 + j];
    }
    if(tid<16){
        bias_s[tid]    = enc_mu_b[rank*16+tid];
        bias_s[16+tid] = enc_sg_b[rank*16+tid];
        bias_s[32+tid] = phi_z_b [rank*16+tid];
    }
    for(int idx=tid; idx<2*256*8; idx+=512) hT[idx]=0.f;
    if(tid==0){
        mbar_init_(mbE,1); mbar_init_(mbZ,1); mbar_init_(mbZ1,1); mbar_init_(mbH,1);
    }
    __syncthreads();
    CLUSTER_SYNC_();

    float c0_st = 0.f, c1_st = 0.f;

    const int dcol = tid & 127, dseg = tid >> 7;
    const unsigned laE  = smb + (unsigned)S_ET*4u  + (unsigned)rank*512u;
    const unsigned laZ  = smb + (unsigned)S_ZT*4u  + (unsigned)rank*512u;
    const unsigned laZ1 = smb + (unsigned)S_Z1T*4u + (unsigned)rank*512u;
    const unsigned srcA  = smb + (unsigned)S_STA*4u;
    const unsigned srcZ  = smb + (unsigned)S_STZ*4u;
    const unsigned srcZ1 = smb + (unsigned)S_STZ1*4u;
    const unsigned srcH  = smb + (unsigned)S_STH*4u;

    for(int t=0; t<Tt; t++){
        const unsigned par = t & 1;
        float* hTc = hT + (t&1)*2048;
        const unsigned hTn_off = (unsigned)(S_HT + ((t+1)&1)*2048);

        if(tid==0){
            mbar_expect_(mbE,4096); mbar_expect_(mbZ,4096); mbar_expect_(mbZ1,4096);
        }

        // ---- LDG prefetches (independent of h; cover H-exchange tail) ----
        float exv=0.f, epsv=0.f;
        if(tid<128){
            int row=tid>>4, col=tid&15;
            size_t b = ((size_t)(cid*8+row)*Tt + t)*128 + rank*16 + col;
            exv=g_Ex[b]; epsv=eps[b];
        }
        float gxv[8];
        if(tid<128){
            int j=tid&31, rp=tid>>5;
            size_t gb0 = ((size_t)(cid*8+2*rp  )*Tt + t)*1024 + rank*128 + j*4;
            size_t gb1 = ((size_t)(cid*8+2*rp+1)*Tt + t)*1024 + rank*128 + j*4;
            *(float4*)&gxv[0] = *(const float4*)(g_Gx+gb0);
            *(float4*)&gxv[4] = *(const float4*)(g_Gx+gb1);
        }

        // ---- H: wait for previous step's exchange, THEN post this step's expect
        if(t>0) mbar_wait_(mbH, (t-1)&1);
        if(tid==0) mbar_expect_(mbH,8192);

        // store h input for prior/dec epilogues
        if(tid<256){
            int row=tid>>5, j=tid&31;
            g_h[((size_t)t*128 + cid*8 + row)*256 + rank*32 + j] = hTc[(rank*32+j)*8 + row];
        }

        // ---- (a) enc_h: ffma2 over col-pairs, 8 k-segments ----
        {
            int cp=tid&7, row=(tid>>3)&7, seg=tid>>6;
            ull acc=0ull;
            const ull* wp2 = (const ull*)Wenc_s;
            int k0=seg*32;
            #pragma unroll 8
            for(int k=k0;k<k0+32;k++){
                ull w2 = wp2[k*8+cp];
                ull h2 = pack2_(hTc[k*8+row]);
                ffma2_(acc,h2,w2);
            }
            *(ull*)&apX[tid*2] = acc;
        }
        __syncthreads();
        if(tid<128){
            int row=tid>>4, col=tid&15, cp=col>>1, e=col&1;
            float v = exv;
            #pragma unroll
            for(int s=0;s<8;s++) v += apX[(s*64 + row*8 + cp)*2 + e];
            stgA[col*8+row]=fmaxf(v,0.f);
            BARN_(1,128);
            if(tid<8){
                fence_async_();
                blkcp_(mapa_(laE,(unsigned)tid), srcA, 512u, mapa_(mbE,(unsigned)tid));
            }
        }
        // d1 chunk A: h@R overlaps E exchange (warps 4-15 start immediately)
        ull a0=0ull,a1=0ull,a2=0ull,a3=0ull;
        {
            const int kr0=dseg*64;
            #pragma unroll
            for(int kk=kr0;kk<kr0+22;kk++){
                ull w2 = pack2_(R_s[kk*128+dcol]);
                const ulonglong2* hp = (const ulonglong2*)(hTc + kk*8);
                ulonglong2 p0 = hp[0], p1 = hp[1];
                ffma2_(a0,w2,p0.x); ffma2_(a1,w2,p0.y);
                ffma2_(a2,w2,p1.x); ffma2_(a3,w2,p1.y);
            }
        }
        mbar_wait_(mbE, par);

        // ---- (b) enc_mu/enc_sigma as paired ffma2; z local ----
        {
            int col=tid&15, row=(tid>>4)&7, seg=tid>>7;
            ull acc=0ull;
            const ull* wp2 = (const ull*)Wms_s;
            int k0=seg*32;
            #pragma unroll 8
            for(int k=k0;k<k0+32;k++){
                ull w2 = wp2[k*16+col];
                ull e2 = pack2_(eT[k*8+row]);
                ffma2_(acc,e2,w2);
            }
            *(ull*)&apX[tid*2] = acc;
        }
        __syncthreads();
        if(tid<128){
            int row=tid>>4, col=tid&15;
            float mu=bias_s[col], sg=bias_s[16+col];
            #pragma unroll
            for(int s=0;s<4;s++){
                int o=(s*128 + row*16 + col)*2;
                mu += apX[o]; sg += apX[o+1];
            }
            sg = softplus_(sg);
            size_t b = ((size_t)(cid*8+row)*Tt + t)*128 + rank*16 + col;
            out[OFF_EMU+b]=mu; out[OFF_ESG+b]=sg;
            stgZ[col*8+row]=fmaf(sg, epsv, mu);
            BARN_(2,128);
            if(tid<8){
                fence_async_();
                blkcp_(mapa_(laZ,(unsigned)tid), srcZ, 512u, mapa_(mbZ,(unsigned)tid));
            }
        }
        // d1 chunk B: overlaps Z exchange
        {
            const int kr0=dseg*64;
            #pragma unroll
            for(int kk=kr0+22;kk<kr0+43;kk++){
                ull w2 = pack2_(R_s[kk*128+dcol]);
                const ulonglong2* hp = (const ulonglong2*)(hTc + kk*8);
                ulonglong2 p0 = hp[0], p1 = hp[1];
                ffma2_(a0,w2,p0.x); ffma2_(a1,w2,p0.y);
                ffma2_(a2,w2,p1.x); ffma2_(a3,w2,p1.y);
            }
        }
        mbar_wait_(mbZ, par);

        // ---- (c) z1 partials as paired ffma2 (8 col-pairs x 8 rows x 8 segs) ----
        {
            int cp=tid&7, row=(tid>>3)&7, seg=tid>>6;
            ull acc=0ull;
            const ull* wp2 = (const ull*)Wpz_s;
            int k0=seg*16;
            #pragma unroll 8
            for(int k=k0;k<k0+16;k++){
                ull w2 = wp2[k*8+cp];
                ull z2 = pack2_(zT[k*8+row]);
                ffma2_(acc,z2,w2);
            }
            *(ull*)&apX[tid*2] = acc;
        }
        __syncthreads();
        if(tid<128){
            int row=tid>>4, col=tid&15, cp=col>>1, e=col&1;
            float v = bias_s[32+col];
            #pragma unroll
            for(int s=0;s<8;s++) v += apX[(s*64 + row*8 + cp)*2 + e];
            v=fmaxf(v,0.f);
            g_z1[((size_t)t*128 + cid*8 + row)*128 + rank*16 + col] = v;
            if(t==Tt-1) out[(size_t)(cid*8+row)*128 + rank*16 + col] = v;
            stgZ1[col*8+row]=v;
            BARN_(3,128);
            if(tid<8){
                fence_async_();
                blkcp_(mapa_(laZ1,(unsigned)tid), srcZ1, 512u, mapa_(mbZ1,(unsigned)tid));
            }
        }
        // Kz register prefetch + d1 chunk C overlap Z1 exchange
        float w32[32];
        {
            const float4* kp4 = (const float4*)g_Kp;
            #pragma unroll
            for(int u=0;u<8;u++) *(float4*)&w32[u*4] = __ldg(&kp4[(rank*8+u)*512 + tid]);
        }
        {
            const int kr0=dseg*64;
            #pragma unroll
            for(int kk=kr0+43;kk<kr0+64;kk++){
                ull w2 = pack2_(R_s[kk*128+dcol]);
                const ulonglong2* hp = (const ulonglong2*)(hTc + kk*8);
                ulonglong2 p0 = hp[0], p1 = hp[1];
                ffma2_(a0,w2,p0.x); ffma2_(a1,w2,p0.y);
                ffma2_(a2,w2,p1.x); ffma2_(a3,w2,p1.y);
            }
        }
        mbar_wait_(mbZ1, par);

        // ---- (d2) z1@Kz from registers ----
        {
            const int kz0=dseg*32;
            #pragma unroll
            for(int u=0;u<32;u++){
                ull w2 = pack2_(w32[u]);
                const ulonglong2* zp = (const ulonglong2*)(z1T + (kz0+u)*8);
                ulonglong2 p0 = zp[0], p1 = zp[1];
                ffma2_(a0,w2,p0.x); ffma2_(a1,w2,p0.y);
                ffma2_(a2,w2,p1.x); ffma2_(a3,w2,p1.y);
            }
            float r0,r1,r2,r3,r4,r5,r6,r7;
            unpack2_(a0,r0,r1); unpack2_(a1,r2,r3);
            unpack2_(a2,r4,r5); unpack2_(a3,r6,r7);
            float* gpp = gp + dseg*1024 + dcol;
            gpp[0*128]=r0; gpp[1*128]=r1; gpp[2*128]=r2; gpp[3*128]=r3;
            gpp[4*128]=r4; gpp[5*128]=r5; gpp[6*128]=r6; gpp[7*128]=r7;
        }
        __syncthreads();
        if(tid<128){
            int j=tid&31, rp=tid>>5, r0=2*rp, r1=r0+1;
            float gi0=gxv[0], gf0=gxv[1], gg0=gxv[2], go0=gxv[3];
            float gi1=gxv[4], gf1=gxv[5], gg1=gxv[6], go1=gxv[7];
            #pragma unroll
            for(int s=0;s<4;s++){
                const float* p0 = gp + s*1024 + r0*128;
                const float* p1 = gp + s*1024 + r1*128;
                gi0+=p0[j]; gf0+=p0[32+j]; gg0+=p0[64+j]; go0+=p0[96+j];
                gi1+=p1[j]; gf1+=p1[32+j]; gg1+=p1[64+j]; go1+=p1[96+j];
            }
            float iv0=sigmoid_(gi0), fv0=sigmoid_(gf0), gv0=tanhf(gg0), ov0=sigmoid_(go0);
            float iv1=sigmoid_(gi1), fv1=sigmoid_(gf1), gv1=tanhf(gg1), ov1=sigmoid_(go1);
            c0_st = fv0*c0_st + iv0*gv0;
            c1_st = fv1*c1_st + iv1*gv1;
            stgH[j*8+r0] = ov0*tanhf(c0_st);
            stgH[j*8+r1] = ov1*tanhf(c1_st);
        }
        __syncthreads();
        if(tid<8){
            fence_async_();
            unsigned laH = smb + (hTn_off + (unsigned)rank*256u)*4u;
            blkcp_(mapa_(laH,(unsigned)tid), srcH, 1024u, mapa_(mbH,(unsigned)tid));
        }
        // waitH at top of next iteration
    }
    mbar_wait_(mbH, (Tt-1)&1);
    CLUSTER_SYNC_();
}

extern "C" void kernel_launch(void* const* d_in, const int* in_sizes, int n_in,
                              void* d_out, int out_size)
{
    (void)in_sizes;(void)n_in;(void)out_size;
    const float* x           =(const float*)d_in[0];
    const float* eps         =(const float*)d_in[1];
    const float* prior_h_w   =(const float*)d_in[2];
    const float* prior_h_b   =(const float*)d_in[3];
    const float* prior_mu_w  =(const float*)d_in[4];
    const float* prior_mu_b  =(const float*)d_in[5];
    const float* prior_sg_w  =(const float*)d_in[6];
    const float* prior_sg_b  =(const float*)d_in[7];
    const float* phi_x_w     =(const float*)d_in[8];
    const float* phi_x_b     =(const float*)d_in[9];
    const float* enc_h_w     =(const float*)d_in[10];
    const float* enc_h_b     =(const float*)d_in[11];
    const float* enc_mu_w    =(const float*)d_in[12];
    const float* enc_mu_b    =(const float*)d_in[13];
    const float* enc_sg_w    =(const float*)d_in[14];
    const float* enc_sg_b    =(const float*)d_in[15];
    const float* phi_z_w     =(const float*)d_in[16];
    const float* phi_z_b     =(const float*)d_in[17];
    const float* dec_h_w     =(const float*)d_in[18];
    const float* dec_h_b     =(const float*)d_in[19];
    const float* dec_mu_w    =(const float*)d_in[20];
    const float* dec_mu_b    =(const float*)d_in[21];
    const float* dec_sg_w    =(const float*)d_in[22];
    const float* dec_sg_b    =(const float*)d_in[23];
    const float* lstm_kernel =(const float*)d_in[24];
    const float* lstm_rec    =(const float*)d_in[25];
    const float* lstm_bias   =(const float*)d_in[26];
    float* out=(float*)d_out;

    float *pH,*pZ1,*pPH,*pDH;
    cudaGetSymbolAddress((void**)&pH,  g_h);
    cudaGetSymbolAddress((void**)&pZ1, g_z1);
    cudaGetSymbolAddress((void**)&pPH, g_PH);
    cudaGetSymbolAddress((void**)&pDH, g_DH);

    cudaFuncSetAttribute(seq_clu, cudaFuncAttributeMaxDynamicSharedMemorySize, SEQ_SMEM_BYTES);

    // 1. prep (bias folds + coalesced Kz)
    prep_k<<<517,256>>>(lstm_kernel,lstm_bias,enc_h_w,enc_h_b,phi_x_b);
    // 2. fused weights
    wk_k<<<576,256>>>(phi_x_w,lstm_kernel,enc_h_w);
    // 3. fused big input GEMMs (Gx permuted store)
    inputs_k<<<dim3(18,512),256>>>(x);
    // 4. sequential recurrence (launch #4 -> captured by ncu)
    seq_clu<<<128,512,SEQ_SMEM_BYTES>>>(eps, enc_h_w, enc_mu_w,enc_mu_b, enc_sg_w,enc_sg_b,
                                        phi_z_w,phi_z_b, lstm_rec, out);
    // 5-10. epilogues
    gemm_k<<<dim3(2,512),256>>>(pH,256,256, nullptr,0,0, prior_h_w,128, nullptr,0,
                                prior_h_b, pPH,128,1,0);
    gemm_k<<<dim3(2,512),256>>>(pPH,128,128, nullptr,0,0, prior_mu_w,128, nullptr,0,
                                prior_mu_b, out+OFF_PMU,128,0,1);
    gemm_k<<<dim3(2,512),256>>>(pPH,128,128, nullptr,0,0, prior_sg_w,128, nullptr,0,
                                prior_sg_b, out+OFF_PSG,128,2,1);
    gemm_k<<<dim3(2,512),256>>>(pZ1,128,128, pH,256,256, dec_h_w,128, dec_h_w+128*128,128,
                                dec_h_b, pDH,128,1,0);
    gemm_k<<<dim3(2,512),256>>>(pDH,128,128, nullptr,0,0, dec_mu_w,128, nullptr,0,
                                dec_mu_b, out+OFF_DMU,128,0,1);
    gemm_k<<<dim3(2,512),256>>>(pDH,128,128, nullptr,0,0, dec_sg_w,128, nullptr,0,
                                dec_sg_b, out+OFF_DSG,128,2,1);
}